// round 1
// baseline (speedup 1.0000x reference)
#include <cuda_runtime.h>
#include <math.h>

#define BB 2
#define NN 2048
#define CC 1024
#define HH 16
#define HD 64
#define MROWS (BB*NN)      // 4096
#define QKVN  (3*CC)       // 3072

// Scratch (static device allocations — allowed)
__device__ float g_q[BB*HH*NN*HD];
__device__ float g_k[BB*HH*NN*HD];
__device__ float g_v[BB*HH*NN*HD];
__device__ float g_o[BB*NN*CC];

// ---------------------------------------------------------------------------
// QKV GEMM: y = x @ qkv_w + qkv_b, scattered into g_q/g_k/g_v as [B,H,N,hd]
// 64x64 block tile, BK=16, 256 threads, 4x4 register tile per thread.
// ---------------------------------------------------------------------------
__global__ __launch_bounds__(256)
void qkv_gemm_kernel(const float* __restrict__ x,
                     const float* __restrict__ w,
                     const float* __restrict__ bias)
{
    __shared__ float Ast[16][64];   // A transposed: [k][row]
    __shared__ float Bs[16][64];    // B natural:   [k][col]

    const int tid = threadIdx.x;
    const int tx = tid & 15, ty = tid >> 4;
    const int row0 = blockIdx.y * 64;
    const int col0 = blockIdx.x * 64;

    const int ar  = tid >> 2;         // 0..63 (A row in tile)
    const int akc = (tid & 3) * 4;    // 0,4,8,12 (A k offset)
    const int br  = tid >> 4;         // 0..15 (B k row)
    const int bc  = (tid & 15) * 4;   // B col offset

    const float* aptr = x + (size_t)(row0 + ar) * CC + akc;
    const float* bptr = w + (size_t)br * QKVN + col0 + bc;

    float acc[4][4];
    #pragma unroll
    for (int i = 0; i < 4; i++)
        #pragma unroll
        for (int j = 0; j < 4; j++) acc[i][j] = 0.f;

    for (int kt = 0; kt < CC; kt += 16) {
        float4 a4 = *(const float4*)(aptr + kt);
        float4 b4 = *(const float4*)(bptr + (size_t)kt * QKVN);
        Ast[akc + 0][ar] = a4.x;
        Ast[akc + 1][ar] = a4.y;
        Ast[akc + 2][ar] = a4.z;
        Ast[akc + 3][ar] = a4.w;
        *(float4*)&Bs[br][bc] = b4;
        __syncthreads();

        #pragma unroll
        for (int k = 0; k < 16; k++) {
            float4 av = *(float4*)&Ast[k][ty * 4];
            float4 bv = *(float4*)&Bs[k][tx * 4];
            float aa[4] = {av.x, av.y, av.z, av.w};
            float bb[4] = {bv.x, bv.y, bv.z, bv.w};
            #pragma unroll
            for (int i = 0; i < 4; i++)
                #pragma unroll
                for (int j = 0; j < 4; j++)
                    acc[i][j] = fmaf(aa[i], bb[j], acc[i][j]);
        }
        __syncthreads();
    }

    // Epilogue: bias + scatter to [B,H,N,hd] per q/k/v
    #pragma unroll
    for (int i = 0; i < 4; i++) {
        const int gr = row0 + ty * 4 + i;
        const int b  = gr >> 11;            // /2048
        const int n  = gr & 2047;
        #pragma unroll
        for (int j = 0; j < 4; j++) {
            const int gc  = col0 + tx * 4 + j;
            const int s   = gc >> 10;       // 0=q 1=k 2=v
            const int rem = gc & 1023;
            const int h   = rem >> 6;
            const int d   = rem & 63;
            float val = acc[i][j] + bias[gc];
            float* dst = (s == 0) ? g_q : (s == 1) ? g_k : g_v;
            dst[(((size_t)(b * HH + h) * NN) + n) * HD + d] = val;
        }
    }
}

// ---------------------------------------------------------------------------
// RMSNorm over last dim (hd=64), one warp per row. postscale folds 1/sqrt(hd)
// score scaling into q.
// ---------------------------------------------------------------------------
__global__ __launch_bounds__(256)
void rmsnorm_kernel(float* __restrict__ buf, const float* __restrict__ w,
                    float postscale, int nrows)
{
    const int warp = (blockIdx.x * blockDim.x + threadIdx.x) >> 5;
    const int lane = threadIdx.x & 31;
    if (warp >= nrows) return;

    float2 v = *(float2*)&buf[(size_t)warp * HD + lane * 2];
    float ss = v.x * v.x + v.y * v.y;
    #pragma unroll
    for (int o = 16; o; o >>= 1) ss += __shfl_xor_sync(0xffffffffu, ss, o);
    float norm = rsqrtf(ss * (1.0f / HD) + 1e-6f) * postscale;
    float2 o2;
    o2.x = w[lane * 2]     * v.x * norm;
    o2.y = w[lane * 2 + 1] * v.y * norm;
    *(float2*)&buf[(size_t)warp * HD + lane * 2] = o2;
}

// ---------------------------------------------------------------------------
// Flash attention: per block = one (b,h) and a 64-query tile; loop 64-key
// tiles with online softmax. Q/K stored d-major in SMEM. P reuses K buffer.
// Writes output back to [B,N,C] layout in g_o.
// ---------------------------------------------------------------------------
__global__ __launch_bounds__(256)
void attn_kernel()
{
    __shared__ float Qst[64][64];   // [d][q]
    __shared__ float Kst[64][64];   // [d][key]  -> reused as P[r][c]
    __shared__ float Vs[64][64];    // [key][d]

    const int tid = threadIdx.x;
    const int tx = tid & 15, ty = tid >> 4;
    const int bh = blockIdx.y;
    const int b = bh >> 4, h = bh & 15;
    const int qt = blockIdx.x;

    const float* qbase = g_q + ((size_t)bh * NN + qt * 64) * HD;
    const float* kbase = g_k + (size_t)bh * NN * HD;
    const float* vbase = g_v + (size_t)bh * NN * HD;

    const int lr = tid >> 2;          // 0..63 row
    const int lc = (tid & 3) * 4;     // 0,4,8,12

    // Load Q tile transposed (d-major)
    #pragma unroll
    for (int rep = 0; rep < 4; rep++) {
        const int d0 = lc + rep * 16;
        float4 q4 = *(const float4*)(qbase + lr * HD + d0);
        Qst[d0 + 0][lr] = q4.x;
        Qst[d0 + 1][lr] = q4.y;
        Qst[d0 + 2][lr] = q4.z;
        Qst[d0 + 3][lr] = q4.w;
    }

    float m[4], l[4], o[4][4];
    #pragma unroll
    for (int i = 0; i < 4; i++) {
        m[i] = -1e30f; l[i] = 0.f;
        #pragma unroll
        for (int j = 0; j < 4; j++) o[i][j] = 0.f;
    }

    for (int kt = 0; kt < NN / 64; kt++) {
        __syncthreads();  // Qst ready (iter 0) / prev PV done (iter>0)

        // Load K (transposed) and V tiles
        const float* kp = kbase + (size_t)(kt * 64 + lr) * HD;
        const float* vp = vbase + (size_t)(kt * 64 + lr) * HD;
        #pragma unroll
        for (int rep = 0; rep < 4; rep++) {
            const int d0 = lc + rep * 16;
            float4 k4 = *(const float4*)(kp + d0);
            Kst[d0 + 0][lr] = k4.x;
            Kst[d0 + 1][lr] = k4.y;
            Kst[d0 + 2][lr] = k4.z;
            Kst[d0 + 3][lr] = k4.w;
            float4 v4 = *(const float4*)(vp + d0);
            *(float4*)&Vs[lr][d0] = v4;
        }
        __syncthreads();

        // S = Q K^T (q already carries 1/sqrt(hd))
        float s[4][4];
        #pragma unroll
        for (int i = 0; i < 4; i++)
            #pragma unroll
            for (int j = 0; j < 4; j++) s[i][j] = 0.f;

        #pragma unroll 4
        for (int d0 = 0; d0 < 64; d0 += 4) {
            #pragma unroll
            for (int dd = 0; dd < 4; dd++) {
                float4 qq = *(float4*)&Qst[d0 + dd][ty * 4];
                float4 kk = *(float4*)&Kst[d0 + dd][tx * 4];
                float qa[4] = {qq.x, qq.y, qq.z, qq.w};
                float kb[4] = {kk.x, kk.y, kk.z, kk.w};
                #pragma unroll
                for (int i = 0; i < 4; i++)
                    #pragma unroll
                    for (int j = 0; j < 4; j++)
                        s[i][j] = fmaf(qa[i], kb[j], s[i][j]);
            }
        }
        __syncthreads();   // all done reading Kst before P overwrites it

        // Online softmax update (row stats reduced over the 16 tx threads)
        #pragma unroll
        for (int i = 0; i < 4; i++) {
            float mx = fmaxf(fmaxf(s[i][0], s[i][1]), fmaxf(s[i][2], s[i][3]));
            #pragma unroll
            for (int off = 8; off; off >>= 1)
                mx = fmaxf(mx, __shfl_xor_sync(0xffffffffu, mx, off));
            float mnew = fmaxf(m[i], mx);
            float corr = __expf(m[i] - mnew);
            m[i] = mnew;
            float rs = 0.f;
            #pragma unroll
            for (int j = 0; j < 4; j++) {
                s[i][j] = __expf(s[i][j] - mnew);
                rs += s[i][j];
            }
            #pragma unroll
            for (int off = 8; off; off >>= 1)
                rs += __shfl_xor_sync(0xffffffffu, rs, off);
            l[i] = l[i] * corr + rs;
            #pragma unroll
            for (int j = 0; j < 4; j++) o[i][j] *= corr;
        }

        // Write P into Kst buffer as P[r][c]
        float (*Ps)[64] = Kst;
        #pragma unroll
        for (int i = 0; i < 4; i++)
            *(float4*)&Ps[ty * 4 + i][tx * 4] =
                make_float4(s[i][0], s[i][1], s[i][2], s[i][3]);
        __syncthreads();

        // O += P V
        #pragma unroll 4
        for (int j0 = 0; j0 < 64; j0 += 4) {
            float4 pv[4], vv[4];
            #pragma unroll
            for (int i = 0; i < 4; i++) pv[i] = *(float4*)&Ps[ty * 4 + i][j0];
            #pragma unroll
            for (int jj = 0; jj < 4; jj++) vv[jj] = *(float4*)&Vs[j0 + jj][tx * 4];
            #pragma unroll
            for (int i = 0; i < 4; i++) {
                float pa[4] = {pv[i].x, pv[i].y, pv[i].z, pv[i].w};
                #pragma unroll
                for (int jj = 0; jj < 4; jj++) {
                    o[i][0] = fmaf(pa[jj], vv[jj].x, o[i][0]);
                    o[i][1] = fmaf(pa[jj], vv[jj].y, o[i][1]);
                    o[i][2] = fmaf(pa[jj], vv[jj].z, o[i][2]);
                    o[i][3] = fmaf(pa[jj], vv[jj].w, o[i][3]);
                }
            }
        }
    }

    // Normalize and write back to [B,N,C] (un-transpose heads)
    float* obase = g_o + ((size_t)b * NN + qt * 64) * CC + h * HD;
    #pragma unroll
    for (int i = 0; i < 4; i++) {
        const float inv = 1.0f / l[i];
        const int r = ty * 4 + i;
        float4 ov = make_float4(o[i][0] * inv, o[i][1] * inv,
                                o[i][2] * inv, o[i][3] * inv);
        *(float4*)&obase[(size_t)r * CC + tx * 4] = ov;
    }
}

// ---------------------------------------------------------------------------
// Output projection: d_out = g_o @ proj_w + proj_b   (4096x1024x1024)
// ---------------------------------------------------------------------------
__global__ __launch_bounds__(256)
void proj_gemm_kernel(const float* __restrict__ w,
                      const float* __restrict__ bias,
                      float* __restrict__ out)
{
    __shared__ float Ast[16][64];
    __shared__ float Bs[16][64];

    const int tid = threadIdx.x;
    const int tx = tid & 15, ty = tid >> 4;
    const int row0 = blockIdx.y * 64;
    const int col0 = blockIdx.x * 64;

    const int ar  = tid >> 2;
    const int akc = (tid & 3) * 4;
    const int br  = tid >> 4;
    const int bc  = (tid & 15) * 4;

    const float* aptr = g_o + (size_t)(row0 + ar) * CC + akc;
    const float* bptr = w + (size_t)br * CC + col0 + bc;

    float acc[4][4];
    #pragma unroll
    for (int i = 0; i < 4; i++)
        #pragma unroll
        for (int j = 0; j < 4; j++) acc[i][j] = 0.f;

    for (int kt = 0; kt < CC; kt += 16) {
        float4 a4 = *(const float4*)(aptr + kt);
        float4 b4 = *(const float4*)(bptr + (size_t)kt * CC);
        Ast[akc + 0][ar] = a4.x;
        Ast[akc + 1][ar] = a4.y;
        Ast[akc + 2][ar] = a4.z;
        Ast[akc + 3][ar] = a4.w;
        *(float4*)&Bs[br][bc] = b4;
        __syncthreads();

        #pragma unroll
        for (int k = 0; k < 16; k++) {
            float4 av = *(float4*)&Ast[k][ty * 4];
            float4 bv = *(float4*)&Bs[k][tx * 4];
            float aa[4] = {av.x, av.y, av.z, av.w};
            float bb[4] = {bv.x, bv.y, bv.z, bv.w};
            #pragma unroll
            for (int i = 0; i < 4; i++)
                #pragma unroll
                for (int j = 0; j < 4; j++)
                    acc[i][j] = fmaf(aa[i], bb[j], acc[i][j]);
        }
        __syncthreads();
    }

    #pragma unroll
    for (int i = 0; i < 4; i++) {
        const int gr = row0 + ty * 4 + i;
        #pragma unroll
        for (int j = 0; j < 4; j++) {
            const int gc = col0 + tx * 4 + j;
            out[(size_t)gr * CC + gc] = acc[i][j] + bias[gc];
        }
    }
}

// ---------------------------------------------------------------------------
extern "C" void kernel_launch(void* const* d_in, const int* in_sizes, int n_in,
                              void* d_out, int out_size)
{
    const float* x        = (const float*)d_in[0];
    const float* qkv_w    = (const float*)d_in[1];
    const float* qkv_b    = (const float*)d_in[2];
    const float* q_norm_w = (const float*)d_in[3];
    const float* k_norm_w = (const float*)d_in[4];
    const float* proj_w   = (const float*)d_in[5];
    const float* proj_b   = (const float*)d_in[6];
    float* out = (float*)d_out;

    float* gq; cudaGetSymbolAddress((void**)&gq, g_q);
    float* gk; cudaGetSymbolAddress((void**)&gk, g_k);

    // 1) QKV GEMM + scatter
    {
        dim3 grid(QKVN / 64, MROWS / 64);
        qkv_gemm_kernel<<<grid, 256>>>(x, qkv_w, qkv_b);
    }

    // 2) RMSNorm q (fold 1/sqrt(hd)=0.125 into q) and k
    {
        const int nrows = BB * HH * NN;           // 65536
        const int blocks = nrows * 32 / 256;      // 8192
        rmsnorm_kernel<<<blocks, 256>>>(gq, q_norm_w, 0.125f, nrows);
        rmsnorm_kernel<<<blocks, 256>>>(gk, k_norm_w, 1.0f, nrows);
    }

    // 3) Flash attention
    {
        dim3 grid(NN / 64, BB * HH);
        attn_kernel<<<grid, 256>>>();
    }

    // 4) Output projection
    {
        dim3 grid(CC / 64, MROWS / 64);
        proj_gemm_kernel<<<grid, 256>>>(proj_w, proj_b, out);
    }
}

// round 3
// speedup vs baseline: 1.1297x; 1.1297x over previous
#include <cuda_runtime.h>
#include <stdint.h>
#include <math.h>

#define BB 2
#define NN 2048
#define CC 1024
#define HH 16
#define HD 64
#define MROWS (BB*NN)      // 4096
#define QKVN  (3*CC)       // 3072

#define TILE 128
#define BK 16

// attention tiles
#define TQ 128
#define TK 128

// Scratch (static device arrays — allowed)
__device__ float g_q[BB*HH*NN*HD];
__device__ float g_k[BB*HH*NN*HD];
__device__ float g_v[BB*HH*NN*HD];
__device__ float g_o[BB*NN*CC];

// ---------------------------------------------------------------------------
// f32x2 packed helpers (FFMA2 — PTX-only on sm_103a)
// ---------------------------------------------------------------------------
__device__ __forceinline__ uint64_t pack2(float lo, float hi) {
    uint64_t r; asm("mov.b64 %0, {%1, %2};" : "=l"(r) : "f"(lo), "f"(hi)); return r;
}
__device__ __forceinline__ void unpack2(uint64_t p, float& lo, float& hi) {
    asm("mov.b64 {%0, %1}, %2;" : "=f"(lo), "=f"(hi) : "l"(p));
}
__device__ __forceinline__ void fma2(uint64_t& d, uint64_t a, uint64_t b) {
    asm("fma.rn.f32x2 %0, %1, %2, %0;" : "+l"(d) : "l"(a), "l"(b));
}
__device__ __forceinline__ void mul2(uint64_t& d, uint64_t a, uint64_t b) {
    asm("mul.rn.f32x2 %0, %1, %2;" : "=l"(d) : "l"(a), "l"(b));
}
__device__ __forceinline__ float ex2(float x) {
    float r; asm("ex2.approx.f32 %0, %1;" : "=f"(r) : "f"(x)); return r;
}

// ---------------------------------------------------------------------------
// QKV GEMM (+bias +fused RMSNorm on q/k): 128x128 tile, BK=16, 256 threads,
// 8x8 microtile as 4 row-pairs x 8 cols of FFMA2.
// q gets extra 0.125*log2(e) scale (softmax done in base-2 domain).
// ---------------------------------------------------------------------------
__global__ __launch_bounds__(256, 2)
void qkv_gemm_kernel(const float* __restrict__ x,
                     const float* __restrict__ w,
                     const float* __restrict__ bias,
                     const float* __restrict__ qnw,
                     const float* __restrict__ knw)
{
    __shared__ float Ast[BK][TILE];   // [k][row]
    __shared__ float Bs [BK][TILE];   // [k][col]

    const int tid = threadIdx.x;
    const int tx = tid & 15, ty = tid >> 4;
    const int row0 = blockIdx.y * TILE;
    const int col0 = blockIdx.x * TILE;

    const int ar  = tid >> 1;          // 0..127
    const int akc = (tid & 1) * 8;     // 0 / 8
    const int bkr = tid >> 4;          // 0..15
    const int bc  = (tid & 15) * 8;

    const float* ap = x + (size_t)(row0 + ar) * CC + akc;
    const float* bp = w + (size_t)bkr * QKVN + col0 + bc;

    float4 pa0 = *(const float4*)(ap);
    float4 pa1 = *(const float4*)(ap + 4);
    float4 pb0 = *(const float4*)(bp);
    float4 pb1 = *(const float4*)(bp + 4);

    uint64_t acc[4][8];
    #pragma unroll
    for (int i = 0; i < 4; i++)
        #pragma unroll
        for (int j = 0; j < 8; j++) acc[i][j] = 0ull;

    for (int kt = 0; kt < CC; kt += BK) {
        Ast[akc+0][ar] = pa0.x; Ast[akc+1][ar] = pa0.y;
        Ast[akc+2][ar] = pa0.z; Ast[akc+3][ar] = pa0.w;
        Ast[akc+4][ar] = pa1.x; Ast[akc+5][ar] = pa1.y;
        Ast[akc+6][ar] = pa1.z; Ast[akc+7][ar] = pa1.w;
        *(float4*)&Bs[bkr][bc]     = pb0;
        *(float4*)&Bs[bkr][bc + 4] = pb1;
        __syncthreads();

        if (kt + BK < CC) {
            pa0 = *(const float4*)(ap + kt + BK);
            pa1 = *(const float4*)(ap + kt + BK + 4);
            pb0 = *(const float4*)(bp + (size_t)(kt + BK) * QKVN);
            pb1 = *(const float4*)(bp + (size_t)(kt + BK) * QKVN + 4);
        }

        #pragma unroll
        for (int k = 0; k < BK; k++) {
            ulonglong2 a01 = *(const ulonglong2*)&Ast[k][ty*8];
            ulonglong2 a23 = *(const ulonglong2*)&Ast[k][ty*8 + 4];
            float4 b0 = *(const float4*)&Bs[k][tx*8];
            float4 b1 = *(const float4*)&Bs[k][tx*8 + 4];
            uint64_t aa[4] = {a01.x, a01.y, a23.x, a23.y};
            uint64_t bd[8] = {pack2(b0.x,b0.x), pack2(b0.y,b0.y),
                              pack2(b0.z,b0.z), pack2(b0.w,b0.w),
                              pack2(b1.x,b1.x), pack2(b1.y,b1.y),
                              pack2(b1.z,b1.z), pack2(b1.w,b1.w)};
            #pragma unroll
            for (int i = 0; i < 4; i++)
                #pragma unroll
                for (int j = 0; j < 8; j++)
                    fma2(acc[i][j], aa[i], bd[j]);
        }
        __syncthreads();
    }

    // ---- Epilogue: unpack, bias, fused rmsnorm (q/k), scatter ----
    float y[8][8];
    #pragma unroll
    for (int i = 0; i < 4; i++)
        #pragma unroll
        for (int j = 0; j < 8; j++)
            unpack2(acc[i][j], y[2*i][j], y[2*i+1][j]);

    float bv[8];
    #pragma unroll
    for (int j = 0; j < 8; j++) bv[j] = bias[col0 + tx*8 + j];
    #pragma unroll
    for (int r = 0; r < 8; r++)
        #pragma unroll
        for (int j = 0; j < 8; j++) y[r][j] += bv[j];

    const int s = col0 >> 10;            // 0=q 1=k 2=v
    if (s < 2) {
        const float* nw = (s == 0) ? qnw : knw;
        const float postscale = (s == 0) ? 0.125f * 1.4426950408889634f : 1.0f;
        float wv[8];
        const int d0 = (tx & 7) * 8;
        #pragma unroll
        for (int j = 0; j < 8; j++) wv[j] = nw[d0 + j];
        #pragma unroll
        for (int r = 0; r < 8; r++) {
            float ss = 0.f;
            #pragma unroll
            for (int j = 0; j < 8; j++) ss += y[r][j] * y[r][j];
            ss += __shfl_xor_sync(0xffffffffu, ss, 1);
            ss += __shfl_xor_sync(0xffffffffu, ss, 2);
            ss += __shfl_xor_sync(0xffffffffu, ss, 4);
            float nrm = rsqrtf(ss * (1.0f / HD) + 1e-6f) * postscale;
            #pragma unroll
            for (int j = 0; j < 8; j++) y[r][j] *= nrm * wv[j];
        }
    }

    float* dst = (s == 0) ? g_q : (s == 1) ? g_k : g_v;
    const int rem = (col0 & 1023) + tx * 8;   // offset within region
    const int h = rem >> 6;
    const int d = rem & 63;
    #pragma unroll
    for (int r = 0; r < 8; r++) {
        const int gr = row0 + ty*8 + r;
        const int b = gr >> 11;
        const int n = gr & 2047;
        float* base = dst + (((size_t)(b * HH + h) * NN) + n) * HD + d;
        *(float4*)(base)     = make_float4(y[r][0], y[r][1], y[r][2], y[r][3]);
        *(float4*)(base + 4) = make_float4(y[r][4], y[r][5], y[r][6], y[r][7]);
    }
}

// ---------------------------------------------------------------------------
// Flash attention, FFMA2: 128q x 128k tiles, 256 threads.
// Qst/Kst d-major [64][128]; Vs [128][64]; Pt [128][128] XOR-swizzled.
// S micro: 4 q-pairs x 8 keys. PV micro: 4 q-pairs x 4 d.
// Scores already in log2 domain (scale folded into q).
// ---------------------------------------------------------------------------
__global__ __launch_bounds__(256, 1)
void attn_kernel()
{
    extern __shared__ float sm[];
    float* Qst = sm;                       // [64][128]
    float* Kst = sm + 64*128;              // [64][128]
    float* Vs  = sm + 2*64*128;            // [128][64]
    float* Pt  = sm + 2*64*128 + 128*64;   // [128][128] swizzled

    const int tid = threadIdx.x;
    const int tx = tid & 15, ty = tid >> 4;
    const int bh = blockIdx.y;
    const int b = bh >> 4, h = bh & 15;
    const int qt = blockIdx.x;

    const float* qbase = g_q + ((size_t)bh * NN + qt * TQ) * HD;
    const float* kbase = g_k + (size_t)bh * NN * HD;
    const float* vbase = g_v + (size_t)bh * NN * HD;

    // Load Q tile transposed (d-major)
    {
        const int qr = tid >> 1;
        const int dc = (tid & 1) * 32;
        #pragma unroll
        for (int c = 0; c < 8; c++) {
            float4 v = *(const float4*)(qbase + (size_t)qr * HD + dc + c*4);
            Qst[(dc + c*4 + 0)*128 + qr] = v.x;
            Qst[(dc + c*4 + 1)*128 + qr] = v.y;
            Qst[(dc + c*4 + 2)*128 + qr] = v.z;
            Qst[(dc + c*4 + 3)*128 + qr] = v.w;
        }
    }

    float m[8], l[8];
    uint64_t o2[4][4];
    #pragma unroll
    for (int i = 0; i < 8; i++) { m[i] = -1e30f; l[i] = 0.f; }
    #pragma unroll
    for (int i = 0; i < 4; i++)
        #pragma unroll
        for (int j = 0; j < 4; j++) o2[i][j] = 0ull;

    for (int kt = 0; kt < NN / TK; kt++) {
        __syncthreads();   // Q ready / prev PV done with Kst,Vs,Pt

        // Load K (d-major) and V tiles
        {
            const int kr = tid >> 1;
            const int dc = (tid & 1) * 32;
            const float* kp = kbase + (size_t)(kt * TK + kr) * HD + dc;
            #pragma unroll
            for (int c = 0; c < 8; c++) {
                float4 v = *(const float4*)(kp + c*4);
                Kst[(dc + c*4 + 0)*128 + kr] = v.x;
                Kst[(dc + c*4 + 1)*128 + kr] = v.y;
                Kst[(dc + c*4 + 2)*128 + kr] = v.z;
                Kst[(dc + c*4 + 3)*128 + kr] = v.w;
            }
            #pragma unroll
            for (int t = 0; t < 8; t++) {
                const int f = tid + 256 * t;
                const int row = f >> 4;
                const int col = (f & 15) * 4;
                *(float4*)(Vs + row*64 + col) =
                    *(const float4*)(vbase + (size_t)(kt * TK + row) * HD + col);
            }
        }
        __syncthreads();

        // ---- S = Q^T-pairs · K  (4 q-pairs x 8 keys per thread) ----
        uint64_t s2[4][8];
        #pragma unroll
        for (int i = 0; i < 4; i++)
            #pragma unroll
            for (int j = 0; j < 8; j++) s2[i][j] = 0ull;

        #pragma unroll 4
        for (int d = 0; d < HD; d++) {
            ulonglong2 qa = *(const ulonglong2*)(Qst + d*128 + ty*8);
            ulonglong2 qb = *(const ulonglong2*)(Qst + d*128 + ty*8 + 4);
            float4 k0 = *(const float4*)(Kst + d*128 + tx*8);
            float4 k1 = *(const float4*)(Kst + d*128 + tx*8 + 4);
            uint64_t aa[4] = {qa.x, qa.y, qb.x, qb.y};
            uint64_t bd[8] = {pack2(k0.x,k0.x), pack2(k0.y,k0.y),
                              pack2(k0.z,k0.z), pack2(k0.w,k0.w),
                              pack2(k1.x,k1.x), pack2(k1.y,k1.y),
                              pack2(k1.z,k1.z), pack2(k1.w,k1.w)};
            #pragma unroll
            for (int i = 0; i < 4; i++)
                #pragma unroll
                for (int j = 0; j < 8; j++)
                    fma2(s2[i][j], aa[i], bd[j]);
        }

        // ---- online softmax (base-2), write P into swizzled Pt ----
        #pragma unroll
        for (int qp = 0; qp < 4; qp++) {
            const int r0 = 2*qp, r1 = 2*qp + 1;
            float slo[8], shi[8];
            #pragma unroll
            for (int j = 0; j < 8; j++) unpack2(s2[qp][j], slo[j], shi[j]);

            float mx0 = slo[0], mx1 = shi[0];
            #pragma unroll
            for (int j = 1; j < 8; j++) {
                mx0 = fmaxf(mx0, slo[j]);
                mx1 = fmaxf(mx1, shi[j]);
            }
            #pragma unroll
            for (int off = 1; off < 16; off <<= 1) {
                mx0 = fmaxf(mx0, __shfl_xor_sync(0xffffffffu, mx0, off));
                mx1 = fmaxf(mx1, __shfl_xor_sync(0xffffffffu, mx1, off));
            }
            const float mn0 = fmaxf(m[r0], mx0);
            const float mn1 = fmaxf(m[r1], mx1);
            const float c0 = ex2(m[r0] - mn0);
            const float c1 = ex2(m[r1] - mn1);
            m[r0] = mn0; m[r1] = mn1;

            float sum0 = 0.f, sum1 = 0.f;
            #pragma unroll
            for (int j = 0; j < 8; j++) {
                slo[j] = ex2(slo[j] - mn0); sum0 += slo[j];
                shi[j] = ex2(shi[j] - mn1); sum1 += shi[j];
            }
            #pragma unroll
            for (int off = 1; off < 16; off <<= 1) {
                sum0 += __shfl_xor_sync(0xffffffffu, sum0, off);
                sum1 += __shfl_xor_sync(0xffffffffu, sum1, off);
            }
            l[r0] = l[r0] * c0 + sum0;
            l[r1] = l[r1] * c1 + sum1;

            // rescale O pairs
            const uint64_t cc = pack2(c0, c1);
            #pragma unroll
            for (int jd = 0; jd < 4; jd++) {
                uint64_t t;
                mul2(t, o2[qp][jd], cc);
                o2[qp][jd] = t;
            }

            // write pair (row r0, r1) for each of 8 keys into swizzled Pt
            const int q4w = ty*2 + (qp >> 1);
            const int sub = 2 * (qp & 1);
            #pragma unroll
            for (int j = 0; j < 8; j++) {
                const int key = tx*8 + j;
                const int off = key*128 + ((q4w ^ tx) << 2) + sub;
                *(float2*)(Pt + off) = make_float2(slo[j], shi[j]);
            }
        }
        __syncthreads();   // Pt complete

        // ---- O += P · V  (4 q-pairs x 4 d per thread) ----
        #pragma unroll 4
        for (int key = 0; key < TK; key++) {
            const int swz = (key >> 3) & 15;
            ulonglong2 p01 = *(const ulonglong2*)(Pt + key*128 + (((ty*2)     ^ swz) << 2));
            ulonglong2 p23 = *(const ulonglong2*)(Pt + key*128 + (((ty*2 + 1) ^ swz) << 2));
            float4 vv = *(const float4*)(Vs + key*64 + tx*4);
            uint64_t pa[4] = {p01.x, p01.y, p23.x, p23.y};
            uint64_t vd[4] = {pack2(vv.x,vv.x), pack2(vv.y,vv.y),
                              pack2(vv.z,vv.z), pack2(vv.w,vv.w)};
            #pragma unroll
            for (int qp = 0; qp < 4; qp++)
                #pragma unroll
                for (int jd = 0; jd < 4; jd++)
                    fma2(o2[qp][jd], pa[qp], vd[jd]);
        }
    }

    // ---- epilogue: normalize, write to g_o [B,N,C] ----
    #pragma unroll
    for (int qp = 0; qp < 4; qp++) {
        float a0,a1,a2,a3, b0,b1,b2,b3;
        unpack2(o2[qp][0], a0, b0);
        unpack2(o2[qp][1], a1, b1);
        unpack2(o2[qp][2], a2, b2);
        unpack2(o2[qp][3], a3, b3);
        const float inv0 = 1.0f / l[2*qp];
        const float inv1 = 1.0f / l[2*qp + 1];
        const int gq0 = qt * TQ + ty*8 + 2*qp;
        float* p0 = g_o + ((size_t)b * NN + gq0) * CC + h * HD + tx*4;
        float* p1 = p0 + CC;
        *(float4*)p0 = make_float4(a0*inv0, a1*inv0, a2*inv0, a3*inv0);
        *(float4*)p1 = make_float4(b0*inv1, b1*inv1, b2*inv1, b3*inv1);
    }
}

// ---------------------------------------------------------------------------
// Output projection: out = g_o @ proj_w + proj_b (4096x1024x1024), FFMA2.
// ---------------------------------------------------------------------------
__global__ __launch_bounds__(256, 2)
void proj_gemm_kernel(const float* __restrict__ w,
                      const float* __restrict__ bias,
                      float* __restrict__ out)
{
    __shared__ float Ast[BK][TILE];
    __shared__ float Bs [BK][TILE];

    const int tid = threadIdx.x;
    const int tx = tid & 15, ty = tid >> 4;
    const int row0 = blockIdx.y * TILE;
    const int col0 = blockIdx.x * TILE;

    const int ar  = tid >> 1;
    const int akc = (tid & 1) * 8;
    const int bkr = tid >> 4;
    const int bc  = (tid & 15) * 8;

    const float* ap = g_o + (size_t)(row0 + ar) * CC + akc;
    const float* bp = w + (size_t)bkr * CC + col0 + bc;

    float4 pa0 = *(const float4*)(ap);
    float4 pa1 = *(const float4*)(ap + 4);
    float4 pb0 = *(const float4*)(bp);
    float4 pb1 = *(const float4*)(bp + 4);

    uint64_t acc[4][8];
    #pragma unroll
    for (int i = 0; i < 4; i++)
        #pragma unroll
        for (int j = 0; j < 8; j++) acc[i][j] = 0ull;

    for (int kt = 0; kt < CC; kt += BK) {
        Ast[akc+0][ar] = pa0.x; Ast[akc+1][ar] = pa0.y;
        Ast[akc+2][ar] = pa0.z; Ast[akc+3][ar] = pa0.w;
        Ast[akc+4][ar] = pa1.x; Ast[akc+5][ar] = pa1.y;
        Ast[akc+6][ar] = pa1.z; Ast[akc+7][ar] = pa1.w;
        *(float4*)&Bs[bkr][bc]     = pb0;
        *(float4*)&Bs[bkr][bc + 4] = pb1;
        __syncthreads();

        if (kt + BK < CC) {
            pa0 = *(const float4*)(ap + kt + BK);
            pa1 = *(const float4*)(ap + kt + BK + 4);
            pb0 = *(const float4*)(bp + (size_t)(kt + BK) * CC);
            pb1 = *(const float4*)(bp + (size_t)(kt + BK) * CC + 4);
        }

        #pragma unroll
        for (int k = 0; k < BK; k++) {
            ulonglong2 a01 = *(const ulonglong2*)&Ast[k][ty*8];
            ulonglong2 a23 = *(const ulonglong2*)&Ast[k][ty*8 + 4];
            float4 b0 = *(const float4*)&Bs[k][tx*8];
            float4 b1 = *(const float4*)&Bs[k][tx*8 + 4];
            uint64_t aa[4] = {a01.x, a01.y, a23.x, a23.y};
            uint64_t bd[8] = {pack2(b0.x,b0.x), pack2(b0.y,b0.y),
                              pack2(b0.z,b0.z), pack2(b0.w,b0.w),
                              pack2(b1.x,b1.x), pack2(b1.y,b1.y),
                              pack2(b1.z,b1.z), pack2(b1.w,b1.w)};
            #pragma unroll
            for (int i = 0; i < 4; i++)
                #pragma unroll
                for (int j = 0; j < 8; j++)
                    fma2(acc[i][j], aa[i], bd[j]);
        }
        __syncthreads();
    }

    float bv[8];
    #pragma unroll
    for (int j = 0; j < 8; j++) bv[j] = bias[col0 + tx*8 + j];

    #pragma unroll
    for (int i = 0; i < 4; i++) {
        float ylo[8], yhi[8];
        #pragma unroll
        for (int j = 0; j < 8; j++) unpack2(acc[i][j], ylo[j], yhi[j]);
        const int gr = row0 + ty*8 + 2*i;
        float* p0 = out + (size_t)gr * CC + col0 + tx*8;
        float* p1 = p0 + CC;
        *(float4*)(p0)     = make_float4(ylo[0]+bv[0], ylo[1]+bv[1], ylo[2]+bv[2], ylo[3]+bv[3]);
        *(float4*)(p0 + 4) = make_float4(ylo[4]+bv[4], ylo[5]+bv[5], ylo[6]+bv[6], ylo[7]+bv[7]);
        *(float4*)(p1)     = make_float4(yhi[0]+bv[0], yhi[1]+bv[1], yhi[2]+bv[2], yhi[3]+bv[3]);
        *(float4*)(p1 + 4) = make_float4(yhi[4]+bv[4], yhi[5]+bv[5], yhi[6]+bv[6], yhi[7]+bv[7]);
    }
}

// ---------------------------------------------------------------------------
extern "C" void kernel_launch(void* const* d_in, const int* in_sizes, int n_in,
                              void* d_out, int out_size)
{
    const float* x        = (const float*)d_in[0];
    const float* qkv_w    = (const float*)d_in[1];
    const float* qkv_b    = (const float*)d_in[2];
    const float* q_norm_w = (const float*)d_in[3];
    const float* k_norm_w = (const float*)d_in[4];
    const float* proj_w   = (const float*)d_in[5];
    const float* proj_b   = (const float*)d_in[6];
    float* out = (float*)d_out;

    const int attn_smem = (2*64*128 + 128*64 + 128*128) * 4;   // 163840 B
    cudaFuncSetAttribute(attn_kernel,
                         cudaFuncAttributeMaxDynamicSharedMemorySize, attn_smem);

    {   // QKV GEMM + bias + fused rmsnorm
        dim3 grid(QKVN / TILE, MROWS / TILE);   // 24 x 32
        qkv_gemm_kernel<<<grid, 256>>>(x, qkv_w, qkv_b, q_norm_w, k_norm_w);
    }
    {   // Flash attention
        dim3 grid(NN / TQ, BB * HH);            // 16 x 32
        attn_kernel<<<grid, 256, attn_smem>>>();
    }
    {   // Output projection
        dim3 grid(CC / TILE, MROWS / TILE);     // 8 x 32
        proj_gemm_kernel<<<grid, 256>>>(proj_w, proj_b, out);
    }
}

// round 6
// speedup vs baseline: 1.4819x; 1.3117x over previous
#include <cuda_runtime.h>
#include <cuda_bf16.h>
#include <stdint.h>
#include <math.h>

#define BB 2
#define NN 2048
#define CC 1024
#define HH 16
#define HD 64
#define MROWS (BB*NN)      // 4096
#define QKVN  (3*CC)       // 3072

// attention tiles
#define TQ 128
#define TK 128

// Scratch (static device arrays — allowed)
__device__ float g_q[BB*HH*NN*HD];
__device__ float g_k[BB*HH*NN*HD];
__device__ float g_v[BB*HH*NN*HD];
__device__ float g_o[BB*NN*CC];
__device__ float g_wt[QKVN*CC];    // qkv_w transposed [3072][1024]
__device__ float g_pwt[CC*CC];     // proj_w transposed [1024][1024]

// ---------------------------------------------------------------------------
// helpers
// ---------------------------------------------------------------------------
__device__ __forceinline__ uint32_t smem_to_u32(const void* p) {
    uint32_t a;
    asm("{ .reg .u64 t; cvta.to.shared.u64 t, %1; cvt.u32.u64 %0, t; }"
        : "=r"(a) : "l"(p));
    return a;
}

__device__ __forceinline__ void ldsm4(uint32_t addr, uint32_t* r) {
    asm volatile("ldmatrix.sync.aligned.m8n8.x4.shared.b16 {%0,%1,%2,%3}, [%4];"
                 : "=r"(r[0]), "=r"(r[1]), "=r"(r[2]), "=r"(r[3]) : "r"(addr));
}

__device__ __forceinline__ void mma16816(float* d, const uint32_t* a,
                                         const uint32_t* b) {
    asm volatile(
        "mma.sync.aligned.m16n8k16.row.col.f32.bf16.bf16.f32 "
        "{%0,%1,%2,%3}, {%4,%5,%6,%7}, {%8,%9}, {%0,%1,%2,%3};"
        : "+f"(d[0]), "+f"(d[1]), "+f"(d[2]), "+f"(d[3])
        : "r"(a[0]), "r"(a[1]), "r"(a[2]), "r"(a[3]), "r"(b[0]), "r"(b[1]));
}

// FFMA2 packed helpers (attention)
__device__ __forceinline__ uint64_t pack2(float lo, float hi) {
    uint64_t r; asm("mov.b64 %0, {%1, %2};" : "=l"(r) : "f"(lo), "f"(hi)); return r;
}
__device__ __forceinline__ void unpack2(uint64_t p, float& lo, float& hi) {
    asm("mov.b64 {%0, %1}, %2;" : "=f"(lo), "=f"(hi) : "l"(p));
}
__device__ __forceinline__ void fma2(uint64_t& d, uint64_t a, uint64_t b) {
    asm("fma.rn.f32x2 %0, %1, %2, %0;" : "+l"(d) : "l"(a), "l"(b));
}
__device__ __forceinline__ void mul2(uint64_t& d, uint64_t a, uint64_t b) {
    asm("mul.rn.f32x2 %0, %1, %2;" : "=l"(d) : "l"(a), "l"(b));
}
__device__ __forceinline__ float ex2(float x) {
    float r; asm("ex2.approx.f32 %0, %1;" : "=f"(r) : "f"(x)); return r;
}

// ---------------------------------------------------------------------------
// Weight transpose: src [R][C] -> dst [C][R]
// ---------------------------------------------------------------------------
__global__ __launch_bounds__(256)
void transpose_kernel(const float* __restrict__ src, float* __restrict__ dst,
                      int R, int C)
{
    __shared__ float t[32][33];
    const int bx = blockIdx.x * 32;
    const int by = blockIdx.y * 32;
    const int x = threadIdx.x, y0 = threadIdx.y;
    #pragma unroll
    for (int i = y0; i < 32; i += 8)
        t[i][x] = src[(size_t)(by + i) * C + bx + x];
    __syncthreads();
    #pragma unroll
    for (int i = y0; i < 32; i += 8)
        dst[(size_t)(bx + i) * R + by + x] = t[x][i];
}

// ---------------------------------------------------------------------------
// HMMA GEMM, bf16 2-term split: D[128,128] = A[128,K] * Bt[128,K]^T
// 256 threads = 8 warps (4 along M x 2 along N), warp tile 32x64, BK=32.
// SMEM per stage: Ahi/Alo/Bhi/Blo each [128 rows][32 bf16] XOR-swizzled.
// mode 0: QKV epilogue (bias + fused rmsnorm on q/k, scatter to g_q/g_k/g_v)
// mode 1: proj epilogue (bias, store row-major)
// ---------------------------------------------------------------------------
__device__ __forceinline__ void store_hilo(char* hi, char* lo, uint32_t off, float4 f) {
    __nv_bfloat16 h0 = __float2bfloat16_rn(f.x);
    __nv_bfloat16 h1 = __float2bfloat16_rn(f.y);
    __nv_bfloat16 h2 = __float2bfloat16_rn(f.z);
    __nv_bfloat16 h3 = __float2bfloat16_rn(f.w);
    float r0 = f.x - __bfloat162float(h0);
    float r1 = f.y - __bfloat162float(h1);
    float r2 = f.z - __bfloat162float(h2);
    float r3 = f.w - __bfloat162float(h3);
    uint2 hp, lp;
    hp.x = ((uint32_t)__bfloat16_as_ushort(h1) << 16) | __bfloat16_as_ushort(h0);
    hp.y = ((uint32_t)__bfloat16_as_ushort(h3) << 16) | __bfloat16_as_ushort(h2);
    asm("cvt.rn.bf16x2.f32 %0, %1, %2;" : "=r"(lp.x) : "f"(r1), "f"(r0));
    asm("cvt.rn.bf16x2.f32 %0, %1, %2;" : "=r"(lp.y) : "f"(r3), "f"(r2));
    *(uint2*)(hi + off) = hp;
    *(uint2*)(lo + off) = lp;
}

// swizzled byte offset inside a [128][32] bf16 buffer (64B rows)
__device__ __forceinline__ uint32_t swz(int row, int kbyte) {
    return (uint32_t)(row * 64 + ((kbyte & 48) ^ (((row >> 1) & 3) << 4)) + (kbyte & 15));
}

__global__ __launch_bounds__(256, 2)
void hmma_gemm_kernel(const float* __restrict__ A, const float* __restrict__ Bt,
                      const float* __restrict__ bias, float* __restrict__ out,
                      const float* __restrict__ qnw, const float* __restrict__ knw,
                      int mode)
{
    __shared__ __align__(128) char sb[32768];
    char* Ahi = sb;
    char* Alo = sb + 8192;
    char* Bhi = sb + 16384;
    char* Blo = sb + 24576;
    const uint32_t sbu = smem_to_u32(sb);

    const int tid  = threadIdx.x;
    const int lane = tid & 31;
    const int w    = tid >> 5;
    const int wm   = (w >> 1) * 32;
    const int wn   = (w & 1) * 64;
    const int row0 = blockIdx.y * 128;
    const int col0 = blockIdx.x * 128;

    const int lrow = tid >> 1;
    const int lk   = (tid & 1) * 16;
    const float* ap = A  + (size_t)(row0 + lrow) * CC + lk;
    const float* bp = Bt + (size_t)(col0 + lrow) * CC + lk;

    float D[2][8][4];
    #pragma unroll
    for (int i = 0; i < 2; i++)
        #pragma unroll
        for (int j = 0; j < 8; j++)
            #pragma unroll
            for (int c = 0; c < 4; c++) D[i][j][c] = 0.f;

    // precompute ldmatrix lane address components
    const int amat = lane >> 3;              // 0..3
    const int arow_off = (amat & 1) * 8 + (lane & 7);
    const int akb_off  = (amat >> 1) * 16;
    const int brow_off = (amat >> 1) * 8 + (lane & 7);
    const int bkb_off  = (amat & 1) * 16;

    const int qsw = ((lrow >> 1) & 3) << 4;

    for (int kt = 0; kt < CC; kt += 32) {
        // ---- load stage: 32 k-floats per row, hi/lo bf16, swizzled ----
        {
            float4 fa[4], fb[4];
            #pragma unroll
            for (int c = 0; c < 4; c++) fa[c] = *(const float4*)(ap + kt + c*4);
            #pragma unroll
            for (int c = 0; c < 4; c++) fb[c] = *(const float4*)(bp + kt + c*4);
            #pragma unroll
            for (int c = 0; c < 4; c++) {
                const int kbyte = (lk + c*4) * 2;
                const uint32_t off = (uint32_t)(lrow*64 + ((kbyte & 48) ^ qsw) + (kbyte & 15));
                store_hilo(Ahi, Alo, off, fa[c]);
                store_hilo(Bhi, Blo, off, fb[c]);
            }
        }
        __syncthreads();

        #pragma unroll
        for (int k16 = 0; k16 < 2; k16++) {
            const int kb = k16 * 32;
            uint32_t a_hi[2][4], a_lo[2][4];
            #pragma unroll
            for (int i = 0; i < 2; i++) {
                const int arow = wm + 16*i + arow_off;
                const uint32_t aoff = swz(arow, kb + akb_off);
                ldsm4(sbu + aoff, a_hi[i]);          // Ahi at base 0
                ldsm4(sbu + 8192 + aoff, a_lo[i]);
            }
            #pragma unroll
            for (int j2 = 0; j2 < 4; j2++) {
                const int brow = wn + j2*16 + brow_off;
                const uint32_t boff = swz(brow, kb + bkb_off);
                uint32_t b_hi[4], b_lo[4];
                ldsm4(sbu + 16384 + boff, b_hi);
                ldsm4(sbu + 24576 + boff, b_lo);
                #pragma unroll
                for (int i = 0; i < 2; i++) {
                    mma16816(D[i][2*j2],   a_hi[i], b_hi);
                    mma16816(D[i][2*j2],   a_hi[i], b_lo);
                    mma16816(D[i][2*j2],   a_lo[i], b_hi);
                    mma16816(D[i][2*j2+1], a_hi[i], b_hi + 2);
                    mma16816(D[i][2*j2+1], a_hi[i], b_lo + 2);
                    mma16816(D[i][2*j2+1], a_lo[i], b_hi + 2);
                }
            }
        }
        __syncthreads();
    }

    // ---- Epilogue ----
    const int g = lane >> 2;
    const int t = lane & 3;
    const int colw = col0 + wn;               // 64-aligned
    const int s   = (mode == 0) ? (colw >> 10) : 3;
    const int h   = (colw & 1023) >> 6;
    float* dst = (mode == 0) ? ((s == 0) ? g_q : (s == 1) ? g_k : g_v) : out;
    const float* nw = (s == 0) ? qnw : knw;
    const float postscale = (s == 0) ? 0.18033688011112042f : 1.0f; // 0.125*log2(e)

    #pragma unroll
    for (int i = 0; i < 2; i++) {
        float v0[16], v1[16];
        #pragma unroll
        for (int j = 0; j < 8; j++) {
            const float bj0 = bias[colw + 8*j + 2*t];
            const float bj1 = bias[colw + 8*j + 2*t + 1];
            v0[2*j]   = D[i][j][0] + bj0;
            v0[2*j+1] = D[i][j][1] + bj1;
            v1[2*j]   = D[i][j][2] + bj0;
            v1[2*j+1] = D[i][j][3] + bj1;
        }
        if (mode == 0 && s < 2) {
            float ss0 = 0.f, ss1 = 0.f;
            #pragma unroll
            for (int c = 0; c < 16; c++) { ss0 += v0[c]*v0[c]; ss1 += v1[c]*v1[c]; }
            ss0 += __shfl_xor_sync(0xffffffffu, ss0, 1);
            ss0 += __shfl_xor_sync(0xffffffffu, ss0, 2);
            ss1 += __shfl_xor_sync(0xffffffffu, ss1, 1);
            ss1 += __shfl_xor_sync(0xffffffffu, ss1, 2);
            const float n0 = rsqrtf(ss0 * (1.0f/64.0f) + 1e-6f) * postscale;
            const float n1 = rsqrtf(ss1 * (1.0f/64.0f) + 1e-6f) * postscale;
            #pragma unroll
            for (int j = 0; j < 8; j++) {
                const float w0 = nw[8*j + 2*t], w1 = nw[8*j + 2*t + 1];
                v0[2*j]   *= n0 * w0;  v0[2*j+1] *= n0 * w1;
                v1[2*j]   *= n1 * w0;  v1[2*j+1] *= n1 * w1;
            }
        }
        const int gr0 = row0 + wm + 16*i + g;
        const int gr1 = gr0 + 8;
        if (mode == 0) {
            const int b0r = gr0 >> 11, n0r = gr0 & 2047;
            const int b1r = gr1 >> 11, n1r = gr1 & 2047;
            float* p0 = dst + (((size_t)(b0r * HH + h) * NN) + n0r) * HD;
            float* p1 = dst + (((size_t)(b1r * HH + h) * NN) + n1r) * HD;
            #pragma unroll
            for (int j = 0; j < 8; j++) {
                *(float2*)(p0 + 8*j + 2*t) = make_float2(v0[2*j], v0[2*j+1]);
                *(float2*)(p1 + 8*j + 2*t) = make_float2(v1[2*j], v1[2*j+1]);
            }
        } else {
            float* p0 = out + (size_t)gr0 * CC + colw;
            float* p1 = out + (size_t)gr1 * CC + colw;
            #pragma unroll
            for (int j = 0; j < 8; j++) {
                *(float2*)(p0 + 8*j + 2*t) = make_float2(v0[2*j], v0[2*j+1]);
                *(float2*)(p1 + 8*j + 2*t) = make_float2(v1[2*j], v1[2*j+1]);
            }
        }
    }
}

// ---------------------------------------------------------------------------
// Flash attention (FFMA2, unchanged): 128q x 128k tiles, 256 threads.
// ---------------------------------------------------------------------------
__global__ __launch_bounds__(256, 1)
void attn_kernel()
{
    extern __shared__ float sm[];
    float* Qst = sm;                       // [64][128]
    float* Kst = sm + 64*128;              // [64][128]
    float* Vs  = sm + 2*64*128;            // [128][64]
    float* Pt  = sm + 2*64*128 + 128*64;   // [128][128] swizzled

    const int tid = threadIdx.x;
    const int tx = tid & 15, ty = tid >> 4;
    const int bh = blockIdx.y;
    const int b = bh >> 4, h = bh & 15;
    const int qt = blockIdx.x;

    const float* qbase = g_q + ((size_t)bh * NN + qt * TQ) * HD;
    const float* kbase = g_k + (size_t)bh * NN * HD;
    const float* vbase = g_v + (size_t)bh * NN * HD;

    {
        const int qr = tid >> 1;
        const int dc = (tid & 1) * 32;
        #pragma unroll
        for (int c = 0; c < 8; c++) {
            float4 v = *(const float4*)(qbase + (size_t)qr * HD + dc + c*4);
            Qst[(dc + c*4 + 0)*128 + qr] = v.x;
            Qst[(dc + c*4 + 1)*128 + qr] = v.y;
            Qst[(dc + c*4 + 2)*128 + qr] = v.z;
            Qst[(dc + c*4 + 3)*128 + qr] = v.w;
        }
    }

    float m[8], l[8];
    uint64_t o2[4][4];
    #pragma unroll
    for (int i = 0; i < 8; i++) { m[i] = -1e30f; l[i] = 0.f; }
    #pragma unroll
    for (int i = 0; i < 4; i++)
        #pragma unroll
        for (int j = 0; j < 4; j++) o2[i][j] = 0ull;

    for (int kt = 0; kt < NN / TK; kt++) {
        __syncthreads();

        {
            const int kr = tid >> 1;
            const int dc = (tid & 1) * 32;
            const float* kp = kbase + (size_t)(kt * TK + kr) * HD + dc;
            #pragma unroll
            for (int c = 0; c < 8; c++) {
                float4 v = *(const float4*)(kp + c*4);
                Kst[(dc + c*4 + 0)*128 + kr] = v.x;
                Kst[(dc + c*4 + 1)*128 + kr] = v.y;
                Kst[(dc + c*4 + 2)*128 + kr] = v.z;
                Kst[(dc + c*4 + 3)*128 + kr] = v.w;
            }
            #pragma unroll
            for (int t = 0; t < 8; t++) {
                const int f = tid + 256 * t;
                const int row = f >> 4;
                const int col = (f & 15) * 4;
                *(float4*)(Vs + row*64 + col) =
                    *(const float4*)(vbase + (size_t)(kt * TK + row) * HD + col);
            }
        }
        __syncthreads();

        uint64_t s2[4][8];
        #pragma unroll
        for (int i = 0; i < 4; i++)
            #pragma unroll
            for (int j = 0; j < 8; j++) s2[i][j] = 0ull;

        #pragma unroll 4
        for (int d = 0; d < HD; d++) {
            ulonglong2 qa = *(const ulonglong2*)(Qst + d*128 + ty*8);
            ulonglong2 qb = *(const ulonglong2*)(Qst + d*128 + ty*8 + 4);
            float4 k0 = *(const float4*)(Kst + d*128 + tx*8);
            float4 k1 = *(const float4*)(Kst + d*128 + tx*8 + 4);
            uint64_t aa[4] = {qa.x, qa.y, qb.x, qb.y};
            uint64_t bd[8] = {pack2(k0.x,k0.x), pack2(k0.y,k0.y),
                              pack2(k0.z,k0.z), pack2(k0.w,k0.w),
                              pack2(k1.x,k1.x), pack2(k1.y,k1.y),
                              pack2(k1.z,k1.z), pack2(k1.w,k1.w)};
            #pragma unroll
            for (int i = 0; i < 4; i++)
                #pragma unroll
                for (int j = 0; j < 8; j++)
                    fma2(s2[i][j], aa[i], bd[j]);
        }

        #pragma unroll
        for (int qp = 0; qp < 4; qp++) {
            const int r0 = 2*qp, r1 = 2*qp + 1;
            float slo[8], shi[8];
            #pragma unroll
            for (int j = 0; j < 8; j++) unpack2(s2[qp][j], slo[j], shi[j]);

            float mx0 = slo[0], mx1 = shi[0];
            #pragma unroll
            for (int j = 1; j < 8; j++) {
                mx0 = fmaxf(mx0, slo[j]);
                mx1 = fmaxf(mx1, shi[j]);
            }
            #pragma unroll
            for (int off = 1; off < 16; off <<= 1) {
                mx0 = fmaxf(mx0, __shfl_xor_sync(0xffffffffu, mx0, off));
                mx1 = fmaxf(mx1, __shfl_xor_sync(0xffffffffu, mx1, off));
            }
            const float mn0 = fmaxf(m[r0], mx0);
            const float mn1 = fmaxf(m[r1], mx1);
            const float c0 = ex2(m[r0] - mn0);
            const float c1 = ex2(m[r1] - mn1);
            m[r0] = mn0; m[r1] = mn1;

            float sum0 = 0.f, sum1 = 0.f;
            #pragma unroll
            for (int j = 0; j < 8; j++) {
                slo[j] = ex2(slo[j] - mn0); sum0 += slo[j];
                shi[j] = ex2(shi[j] - mn1); sum1 += shi[j];
            }
            #pragma unroll
            for (int off = 1; off < 16; off <<= 1) {
                sum0 += __shfl_xor_sync(0xffffffffu, sum0, off);
                sum1 += __shfl_xor_sync(0xffffffffu, sum1, off);
            }
            l[r0] = l[r0] * c0 + sum0;
            l[r1] = l[r1] * c1 + sum1;

            const uint64_t cc = pack2(c0, c1);
            #pragma unroll
            for (int jd = 0; jd < 4; jd++) {
                uint64_t t;
                mul2(t, o2[qp][jd], cc);
                o2[qp][jd] = t;
            }

            const int q4w = ty*2 + (qp >> 1);
            const int sub = 2 * (qp & 1);
            #pragma unroll
            for (int j = 0; j < 8; j++) {
                const int key = tx*8 + j;
                const int off = key*128 + ((q4w ^ tx) << 2) + sub;
                *(float2*)(Pt + off) = make_float2(slo[j], shi[j]);
            }
        }
        __syncthreads();

        #pragma unroll 4
        for (int key = 0; key < TK; key++) {
            const int swzk = (key >> 3) & 15;
            ulonglong2 p01 = *(const ulonglong2*)(Pt + key*128 + (((ty*2)     ^ swzk) << 2));
            ulonglong2 p23 = *(const ulonglong2*)(Pt + key*128 + (((ty*2 + 1) ^ swzk) << 2));
            float4 vv = *(const float4*)(Vs + key*64 + tx*4);
            uint64_t pa[4] = {p01.x, p01.y, p23.x, p23.y};
            uint64_t vd[4] = {pack2(vv.x,vv.x), pack2(vv.y,vv.y),
                              pack2(vv.z,vv.z), pack2(vv.w,vv.w)};
            #pragma unroll
            for (int qp = 0; qp < 4; qp++)
                #pragma unroll
                for (int jd = 0; jd < 4; jd++)
                    fma2(o2[qp][jd], pa[qp], vd[jd]);
        }
    }

    #pragma unroll
    for (int qp = 0; qp < 4; qp++) {
        float a0,a1,a2,a3, b0,b1,b2,b3;
        unpack2(o2[qp][0], a0, b0);
        unpack2(o2[qp][1], a1, b1);
        unpack2(o2[qp][2], a2, b2);
        unpack2(o2[qp][3], a3, b3);
        const float inv0 = 1.0f / l[2*qp];
        const float inv1 = 1.0f / l[2*qp + 1];
        const int gq0 = qt * TQ + ty*8 + 2*qp;
        float* p0 = g_o + ((size_t)b * NN + gq0) * CC + h * HD + tx*4;
        float* p1 = p0 + CC;
        *(float4*)p0 = make_float4(a0*inv0, a1*inv0, a2*inv0, a3*inv0);
        *(float4*)p1 = make_float4(b0*inv1, b1*inv1, b2*inv1, b3*inv1);
    }
}

// ---------------------------------------------------------------------------
extern "C" void kernel_launch(void* const* d_in, const int* in_sizes, int n_in,
                              void* d_out, int out_size)
{
    const float* x        = (const float*)d_in[0];
    const float* qkv_w    = (const float*)d_in[1];
    const float* qkv_b    = (const float*)d_in[2];
    const float* q_norm_w = (const float*)d_in[3];
    const float* k_norm_w = (const float*)d_in[4];
    const float* proj_w   = (const float*)d_in[5];
    const float* proj_b   = (const float*)d_in[6];
    float* out = (float*)d_out;

    float *wt, *pwt, *go;
    cudaGetSymbolAddress((void**)&wt,  g_wt);
    cudaGetSymbolAddress((void**)&pwt, g_pwt);
    cudaGetSymbolAddress((void**)&go,  g_o);

    const int attn_smem = (2*64*128 + 128*64 + 128*128) * 4;   // 163840 B
    cudaFuncSetAttribute(attn_kernel,
                         cudaFuncAttributeMaxDynamicSharedMemorySize, attn_smem);

    // Weight transposes (N-major -> K-major)
    {
        dim3 tb(32, 8);
        transpose_kernel<<<dim3(QKVN/32, CC/32), tb>>>(qkv_w, wt, CC, QKVN);
        transpose_kernel<<<dim3(CC/32, CC/32), tb>>>(proj_w, pwt, CC, CC);
    }
    // QKV GEMM + bias + fused rmsnorm (HMMA bf16 split)
    {
        dim3 grid(QKVN / 128, MROWS / 128);   // 24 x 32
        hmma_gemm_kernel<<<grid, 256>>>(x, wt, qkv_b, nullptr,
                                        q_norm_w, k_norm_w, 0);
    }
    // Flash attention (FFMA2)
    {
        dim3 grid(NN / TQ, BB * HH);          // 16 x 32
        attn_kernel<<<grid, 256, attn_smem>>>();
    }
    // Output projection (HMMA bf16 split)
    {
        dim3 grid(CC / 128, MROWS / 128);     // 8 x 32
        hmma_gemm_kernel<<<grid, 256>>>(go, pwt, proj_b, out,
                                        nullptr, nullptr, 1);
    }
}

// round 7
// speedup vs baseline: 2.2823x; 1.5401x over previous
#include <cuda_runtime.h>
#include <cuda_bf16.h>
#include <stdint.h>
#include <math.h>

#define BB 2
#define NN 2048
#define CC 1024
#define HH 16
#define HD 64
#define MROWS (BB*NN)      // 4096
#define QKVN  (3*CC)       // 3072

// Scratch (static device arrays — allowed)
__device__ float g_q[BB*HH*NN*HD];
__device__ float g_k[BB*HH*NN*HD];
__device__ float g_v[BB*HH*NN*HD];
__device__ float g_o[BB*NN*CC];
__device__ float g_wt[QKVN*CC];    // qkv_w transposed [3072][1024]
__device__ float g_pwt[CC*CC];     // proj_w transposed [1024][1024]

// ---------------------------------------------------------------------------
// helpers
// ---------------------------------------------------------------------------
__device__ __forceinline__ uint32_t smem_to_u32(const void* p) {
    uint32_t a;
    asm("{ .reg .u64 t; cvta.to.shared.u64 t, %1; cvt.u32.u64 %0, t; }"
        : "=r"(a) : "l"(p));
    return a;
}

__device__ __forceinline__ void ldsm4(uint32_t addr, uint32_t* r) {
    asm volatile("ldmatrix.sync.aligned.m8n8.x4.shared.b16 {%0,%1,%2,%3}, [%4];"
                 : "=r"(r[0]), "=r"(r[1]), "=r"(r[2]), "=r"(r[3]) : "r"(addr));
}

__device__ __forceinline__ void mma16816(float* d, const uint32_t* a,
                                         const uint32_t* b) {
    asm volatile(
        "mma.sync.aligned.m16n8k16.row.col.f32.bf16.bf16.f32 "
        "{%0,%1,%2,%3}, {%4,%5,%6,%7}, {%8,%9}, {%0,%1,%2,%3};"
        : "+f"(d[0]), "+f"(d[1]), "+f"(d[2]), "+f"(d[3])
        : "r"(a[0]), "r"(a[1]), "r"(a[2]), "r"(a[3]), "r"(b[0]), "r"(b[1]));
}

__device__ __forceinline__ float ex2(float x) {
    float r; asm("ex2.approx.f32 %0, %1;" : "=f"(r) : "f"(x)); return r;
}

// pack (p0 low, p1 high) as bf16x2; also emit the bf16 residual pair
__device__ __forceinline__ void split_pair(float p0, float p1,
                                           uint32_t& hi, uint32_t& lo) {
    __nv_bfloat16 h0 = __float2bfloat16_rn(p0);
    __nv_bfloat16 h1 = __float2bfloat16_rn(p1);
    hi = ((uint32_t)__bfloat16_as_ushort(h1) << 16) | __bfloat16_as_ushort(h0);
    float r0 = p0 - __bfloat162float(h0);
    float r1 = p1 - __bfloat162float(h1);
    asm("cvt.rn.bf16x2.f32 %0, %1, %2;" : "=r"(lo) : "f"(r1), "f"(r0));
}

// ---------------------------------------------------------------------------
// Weight transpose: src [R][C] -> dst [C][R]
// ---------------------------------------------------------------------------
__global__ __launch_bounds__(256)
void transpose_kernel(const float* __restrict__ src, float* __restrict__ dst,
                      int R, int C)
{
    __shared__ float t[32][33];
    const int bx = blockIdx.x * 32;
    const int by = blockIdx.y * 32;
    const int x = threadIdx.x, y0 = threadIdx.y;
    #pragma unroll
    for (int i = y0; i < 32; i += 8)
        t[i][x] = src[(size_t)(by + i) * C + bx + x];
    __syncthreads();
    #pragma unroll
    for (int i = y0; i < 32; i += 8)
        dst[(size_t)(bx + i) * R + by + x] = t[x][i];
}

// ---------------------------------------------------------------------------
// HMMA GEMM (unchanged from round 6, validated)
// ---------------------------------------------------------------------------
__device__ __forceinline__ void store_hilo(char* hi, char* lo, uint32_t off, float4 f) {
    __nv_bfloat16 h0 = __float2bfloat16_rn(f.x);
    __nv_bfloat16 h1 = __float2bfloat16_rn(f.y);
    __nv_bfloat16 h2 = __float2bfloat16_rn(f.z);
    __nv_bfloat16 h3 = __float2bfloat16_rn(f.w);
    float r0 = f.x - __bfloat162float(h0);
    float r1 = f.y - __bfloat162float(h1);
    float r2 = f.z - __bfloat162float(h2);
    float r3 = f.w - __bfloat162float(h3);
    uint2 hp, lp;
    hp.x = ((uint32_t)__bfloat16_as_ushort(h1) << 16) | __bfloat16_as_ushort(h0);
    hp.y = ((uint32_t)__bfloat16_as_ushort(h3) << 16) | __bfloat16_as_ushort(h2);
    asm("cvt.rn.bf16x2.f32 %0, %1, %2;" : "=r"(lp.x) : "f"(r1), "f"(r0));
    asm("cvt.rn.bf16x2.f32 %0, %1, %2;" : "=r"(lp.y) : "f"(r3), "f"(r2));
    *(uint2*)(hi + off) = hp;
    *(uint2*)(lo + off) = lp;
}

// swizzled byte offset inside a [128][32] bf16 buffer (64B rows)
__device__ __forceinline__ uint32_t swz(int row, int kbyte) {
    return (uint32_t)(row * 64 + ((kbyte & 48) ^ (((row >> 1) & 3) << 4)) + (kbyte & 15));
}

__global__ __launch_bounds__(256, 2)
void hmma_gemm_kernel(const float* __restrict__ A, const float* __restrict__ Bt,
                      const float* __restrict__ bias, float* __restrict__ out,
                      const float* __restrict__ qnw, const float* __restrict__ knw,
                      int mode)
{
    __shared__ __align__(128) char sb[32768];
    char* Ahi = sb;
    char* Alo = sb + 8192;
    char* Bhi = sb + 16384;
    char* Blo = sb + 24576;
    const uint32_t sbu = smem_to_u32(sb);

    const int tid  = threadIdx.x;
    const int lane = tid & 31;
    const int w    = tid >> 5;
    const int wm   = (w >> 1) * 32;
    const int wn   = (w & 1) * 64;
    const int row0 = blockIdx.y * 128;
    const int col0 = blockIdx.x * 128;

    const int lrow = tid >> 1;
    const int lk   = (tid & 1) * 16;
    const float* ap = A  + (size_t)(row0 + lrow) * CC + lk;
    const float* bp = Bt + (size_t)(col0 + lrow) * CC + lk;

    float D[2][8][4];
    #pragma unroll
    for (int i = 0; i < 2; i++)
        #pragma unroll
        for (int j = 0; j < 8; j++)
            #pragma unroll
            for (int c = 0; c < 4; c++) D[i][j][c] = 0.f;

    const int amat = lane >> 3;
    const int arow_off = (amat & 1) * 8 + (lane & 7);
    const int akb_off  = (amat >> 1) * 16;
    const int brow_off = (amat >> 1) * 8 + (lane & 7);
    const int bkb_off  = (amat & 1) * 16;

    const int qsw = ((lrow >> 1) & 3) << 4;

    for (int kt = 0; kt < CC; kt += 32) {
        {
            float4 fa[4], fb[4];
            #pragma unroll
            for (int c = 0; c < 4; c++) fa[c] = *(const float4*)(ap + kt + c*4);
            #pragma unroll
            for (int c = 0; c < 4; c++) fb[c] = *(const float4*)(bp + kt + c*4);
            #pragma unroll
            for (int c = 0; c < 4; c++) {
                const int kbyte = (lk + c*4) * 2;
                const uint32_t off = (uint32_t)(lrow*64 + ((kbyte & 48) ^ qsw) + (kbyte & 15));
                store_hilo(Ahi, Alo, off, fa[c]);
                store_hilo(Bhi, Blo, off, fb[c]);
            }
        }
        __syncthreads();

        #pragma unroll
        for (int k16 = 0; k16 < 2; k16++) {
            const int kb = k16 * 32;
            uint32_t a_hi[2][4], a_lo[2][4];
            #pragma unroll
            for (int i = 0; i < 2; i++) {
                const int arow = wm + 16*i + arow_off;
                const uint32_t aoff = swz(arow, kb + akb_off);
                ldsm4(sbu + aoff, a_hi[i]);
                ldsm4(sbu + 8192 + aoff, a_lo[i]);
            }
            #pragma unroll
            for (int j2 = 0; j2 < 4; j2++) {
                const int brow = wn + j2*16 + brow_off;
                const uint32_t boff = swz(brow, kb + bkb_off);
                uint32_t b_hi[4], b_lo[4];
                ldsm4(sbu + 16384 + boff, b_hi);
                ldsm4(sbu + 24576 + boff, b_lo);
                #pragma unroll
                for (int i = 0; i < 2; i++) {
                    mma16816(D[i][2*j2],   a_hi[i], b_hi);
                    mma16816(D[i][2*j2],   a_hi[i], b_lo);
                    mma16816(D[i][2*j2],   a_lo[i], b_hi);
                    mma16816(D[i][2*j2+1], a_hi[i], b_hi + 2);
                    mma16816(D[i][2*j2+1], a_hi[i], b_lo + 2);
                    mma16816(D[i][2*j2+1], a_lo[i], b_hi + 2);
                }
            }
        }
        __syncthreads();
    }

    const int g = lane >> 2;
    const int t = lane & 3;
    const int colw = col0 + wn;
    const int s   = (mode == 0) ? (colw >> 10) : 3;
    const int h   = (colw & 1023) >> 6;
    float* dst = (mode == 0) ? ((s == 0) ? g_q : (s == 1) ? g_k : g_v) : out;
    const float* nw = (s == 0) ? qnw : knw;
    const float postscale = (s == 0) ? 0.18033688011112042f : 1.0f; // 0.125*log2(e)

    #pragma unroll
    for (int i = 0; i < 2; i++) {
        float v0[16], v1[16];
        #pragma unroll
        for (int j = 0; j < 8; j++) {
            const float bj0 = bias[colw + 8*j + 2*t];
            const float bj1 = bias[colw + 8*j + 2*t + 1];
            v0[2*j]   = D[i][j][0] + bj0;
            v0[2*j+1] = D[i][j][1] + bj1;
            v1[2*j]   = D[i][j][2] + bj0;
            v1[2*j+1] = D[i][j][3] + bj1;
        }
        if (mode == 0 && s < 2) {
            float ss0 = 0.f, ss1 = 0.f;
            #pragma unroll
            for (int c = 0; c < 16; c++) { ss0 += v0[c]*v0[c]; ss1 += v1[c]*v1[c]; }
            ss0 += __shfl_xor_sync(0xffffffffu, ss0, 1);
            ss0 += __shfl_xor_sync(0xffffffffu, ss0, 2);
            ss1 += __shfl_xor_sync(0xffffffffu, ss1, 1);
            ss1 += __shfl_xor_sync(0xffffffffu, ss1, 2);
            const float n0 = rsqrtf(ss0 * (1.0f/64.0f) + 1e-6f) * postscale;
            const float n1 = rsqrtf(ss1 * (1.0f/64.0f) + 1e-6f) * postscale;
            #pragma unroll
            for (int j = 0; j < 8; j++) {
                const float w0 = nw[8*j + 2*t], w1 = nw[8*j + 2*t + 1];
                v0[2*j]   *= n0 * w0;  v0[2*j+1] *= n0 * w1;
                v1[2*j]   *= n1 * w0;  v1[2*j+1] *= n1 * w1;
            }
        }
        const int gr0 = row0 + wm + 16*i + g;
        const int gr1 = gr0 + 8;
        if (mode == 0) {
            const int b0r = gr0 >> 11, n0r = gr0 & 2047;
            const int b1r = gr1 >> 11, n1r = gr1 & 2047;
            float* p0 = dst + (((size_t)(b0r * HH + h) * NN) + n0r) * HD;
            float* p1 = dst + (((size_t)(b1r * HH + h) * NN) + n1r) * HD;
            #pragma unroll
            for (int j = 0; j < 8; j++) {
                *(float2*)(p0 + 8*j + 2*t) = make_float2(v0[2*j], v0[2*j+1]);
                *(float2*)(p1 + 8*j + 2*t) = make_float2(v1[2*j], v1[2*j+1]);
            }
        } else {
            float* p0 = out + (size_t)gr0 * CC + colw;
            float* p1 = out + (size_t)gr1 * CC + colw;
            #pragma unroll
            for (int j = 0; j < 8; j++) {
                *(float2*)(p0 + 8*j + 2*t) = make_float2(v0[2*j], v0[2*j+1]);
                *(float2*)(p1 + 8*j + 2*t) = make_float2(v1[2*j], v1[2*j+1]);
            }
        }
    }
}

// ---------------------------------------------------------------------------
// HMMA flash attention.
// Block = one (b,h) x 128-q tile; 8 warps, warp = 16 q-rows x ALL 128 keys.
// SMEM (96KB dynamic, hi/lo bf16):
//   Q [128][64] @0/16K, K [128][64] @32K/48K, Vt [64][128] @64K/80K.
// S fragments live in registers and convert directly into PV A-fragments.
// q is pre-scaled by 0.125*log2(e) in QKV epilogue -> softmax via ex2.
// ---------------------------------------------------------------------------
__device__ __forceinline__ uint32_t swz_qk(int row, int kbyte) {   // 128B rows
    return (uint32_t)(row * 128 + ((((kbyte >> 4) ^ row) & 7) << 4) + (kbyte & 15));
}
__device__ __forceinline__ uint32_t swz_v(int row, int kbyte) {    // 256B rows
    return (uint32_t)(row * 256 + (kbyte & 128) +
                      ((((kbyte >> 4) ^ row) & 7) << 4) + (kbyte & 15));
}

#define ATTN_SMEM 98304

__global__ __launch_bounds__(256, 1)
void attn_kernel()
{
    extern __shared__ __align__(128) char smem[];
    char* Qhi  = smem;
    char* Qlo  = smem + 16384;
    char* Khi  = smem + 32768;
    char* Klo  = smem + 49152;
    char* Vthi = smem + 65536;
    char* Vtlo = smem + 81920;
    const uint32_t sbu = smem_to_u32(smem);

    const int tid  = threadIdx.x;
    const int lane = tid & 31;
    const int w    = tid >> 5;
    const int wm   = w * 16;               // warp's 16 q-rows
    const int g = lane >> 2, t = lane & 3;

    const int bh = blockIdx.y;
    const int b  = bh >> 4, h = bh & 15;
    const int qt = blockIdx.x;

    const float* qbase = g_q + ((size_t)bh * NN + qt * 128) * HD;
    const float* kbase = g_k + (size_t)bh * NN * HD;
    const float* vbase = g_v + (size_t)bh * NN * HD;

    const int amat = lane >> 3;
    const int arow_off = (amat & 1) * 8 + (lane & 7);
    const int akb_off  = (amat >> 1) * 16;
    const int brow_off = (amat >> 1) * 8 + (lane & 7);
    const int bkb_off  = (amat & 1) * 16;

    // ---- load Q tile to smem (hi/lo, swizzled) ----
    {
        const int row = tid >> 1;
        const int kh  = (tid & 1) * 32;
        const float* qp = qbase + (size_t)row * HD + kh;
        #pragma unroll
        for (int c = 0; c < 8; c++) {
            float4 f = *(const float4*)(qp + c*4);
            const uint32_t off = swz_qk(row, (kh + c*4) * 2);
            store_hilo(Qhi, Qlo, off, f);
        }
    }
    __syncthreads();

    // ---- Q fragments (16 rows x 64 hd) into registers ----
    uint32_t qh[4][4], ql[4][4];
    #pragma unroll
    for (int kk = 0; kk < 4; kk++) {
        const uint32_t off = swz_qk(wm + arow_off, kk*32 + akb_off);
        ldsm4(sbu + off, qh[kk]);
        ldsm4(sbu + 16384 + off, ql[kk]);
    }

    float m0 = -1e30f, m1 = -1e30f, l0 = 0.f, l1 = 0.f;
    float O[8][4];
    #pragma unroll
    for (int j = 0; j < 8; j++)
        #pragma unroll
        for (int c = 0; c < 4; c++) O[j][c] = 0.f;

    for (int kt = 0; kt < NN / 128; kt++) {
        // ---- load K tile [128][64] ----
        {
            const int row = tid >> 1;
            const int kh  = (tid & 1) * 32;
            const float* kp = kbase + (size_t)(kt * 128 + row) * HD + kh;
            #pragma unroll
            for (int c = 0; c < 8; c++) {
                float4 f = *(const float4*)(kp + c*4);
                const uint32_t off = swz_qk(row, (kh + c*4) * 2);
                store_hilo(Khi, Klo, off, f);
            }
        }
        // ---- load V tile transposed -> Vt [64][128] ----
        {
            const int hd = tid & 63;
            const int kg = tid >> 6;
            #pragma unroll
            for (int ii = 0; ii < 8; ii++) {
                const int k0 = kg * 32 + ii * 4;
                const float* vp = vbase + (size_t)(kt * 128 + k0) * HD + hd;
                float f0 = vp[0], f1 = vp[64], f2 = vp[128], f3 = vp[192];
                uint32_t h01, l01, h23, l23;
                split_pair(f0, f1, h01, l01);
                split_pair(f2, f3, h23, l23);
                const uint32_t off = swz_v(hd, k0 * 2);
                *(uint2*)(Vthi + off) = make_uint2(h01, h23);
                *(uint2*)(Vtlo + off) = make_uint2(l01, l23);
            }
        }
        __syncthreads();

        // ---- S = Q K^T : 16 n-tiles (8 keys each) ----
        float S[16][4];
        #pragma unroll
        for (int j = 0; j < 16; j++)
            #pragma unroll
            for (int c = 0; c < 4; c++) S[j][c] = 0.f;

        #pragma unroll
        for (int kk = 0; kk < 4; kk++) {
            #pragma unroll
            for (int j2 = 0; j2 < 8; j2++) {
                const uint32_t off = swz_qk(j2*16 + brow_off, kk*32 + bkb_off);
                uint32_t bhh[4], bll[4];
                ldsm4(sbu + 32768 + off, bhh);
                ldsm4(sbu + 49152 + off, bll);
                mma16816(S[2*j2],   qh[kk], bhh);
                mma16816(S[2*j2],   qh[kk], bll);
                mma16816(S[2*j2],   ql[kk], bhh);
                mma16816(S[2*j2+1], qh[kk], bhh + 2);
                mma16816(S[2*j2+1], qh[kk], bll + 2);
                mma16816(S[2*j2+1], ql[kk], bhh + 2);
            }
        }

        // ---- online softmax (base-2 domain) ----
        float mx0 = S[0][0], mx1 = S[0][2];
        #pragma unroll
        for (int j = 0; j < 16; j++) {
            mx0 = fmaxf(mx0, fmaxf(S[j][0], S[j][1]));
            mx1 = fmaxf(mx1, fmaxf(S[j][2], S[j][3]));
        }
        mx0 = fmaxf(mx0, __shfl_xor_sync(0xffffffffu, mx0, 1));
        mx0 = fmaxf(mx0, __shfl_xor_sync(0xffffffffu, mx0, 2));
        mx1 = fmaxf(mx1, __shfl_xor_sync(0xffffffffu, mx1, 1));
        mx1 = fmaxf(mx1, __shfl_xor_sync(0xffffffffu, mx1, 2));
        const float mn0 = fmaxf(m0, mx0);
        const float mn1 = fmaxf(m1, mx1);
        const float c0 = ex2(m0 - mn0);
        const float c1 = ex2(m1 - mn1);
        m0 = mn0; m1 = mn1;

        float sum0 = 0.f, sum1 = 0.f;
        #pragma unroll
        for (int j = 0; j < 16; j++) {
            S[j][0] = ex2(S[j][0] - mn0); sum0 += S[j][0];
            S[j][1] = ex2(S[j][1] - mn0); sum0 += S[j][1];
            S[j][2] = ex2(S[j][2] - mn1); sum1 += S[j][2];
            S[j][3] = ex2(S[j][3] - mn1); sum1 += S[j][3];
        }
        sum0 += __shfl_xor_sync(0xffffffffu, sum0, 1);
        sum0 += __shfl_xor_sync(0xffffffffu, sum0, 2);
        sum1 += __shfl_xor_sync(0xffffffffu, sum1, 1);
        sum1 += __shfl_xor_sync(0xffffffffu, sum1, 2);
        l0 = l0 * c0 + sum0;
        l1 = l1 * c1 + sum1;

        #pragma unroll
        for (int j = 0; j < 8; j++) {
            O[j][0] *= c0; O[j][1] *= c0;
            O[j][2] *= c1; O[j][3] *= c1;
        }

        // ---- O += P V  (P from S fragments, in registers) ----
        #pragma unroll
        for (int kk = 0; kk < 8; kk++) {
            uint32_t phi[4], plo[4];
            split_pair(S[2*kk][0],   S[2*kk][1],   phi[0], plo[0]);
            split_pair(S[2*kk][2],   S[2*kk][3],   phi[1], plo[1]);
            split_pair(S[2*kk+1][0], S[2*kk+1][1], phi[2], plo[2]);
            split_pair(S[2*kk+1][2], S[2*kk+1][3], phi[3], plo[3]);
            #pragma unroll
            for (int jh = 0; jh < 4; jh++) {
                const uint32_t off = swz_v(jh*16 + brow_off, kk*32 + bkb_off);
                uint32_t vh[4], vl[4];
                ldsm4(sbu + 65536 + off, vh);
                ldsm4(sbu + 81920 + off, vl);
                mma16816(O[2*jh],   phi, vh);
                mma16816(O[2*jh],   phi, vl);
                mma16816(O[2*jh],   plo, vh);
                mma16816(O[2*jh+1], phi, vh + 2);
                mma16816(O[2*jh+1], phi, vl + 2);
                mma16816(O[2*jh+1], plo, vh + 2);
            }
        }
        __syncthreads();   // PV done before next tile's loads overwrite K/Vt
    }

    // ---- epilogue: normalize, write g_o [B,N,C] ----
    const float inv0 = 1.0f / l0;
    const float inv1 = 1.0f / l1;
    const int q0 = qt * 128 + wm + g;
    const int q1 = q0 + 8;
    float* p0 = g_o + ((size_t)b * NN + q0) * CC + h * HD;
    float* p1 = g_o + ((size_t)b * NN + q1) * CC + h * HD;
    #pragma unroll
    for (int j = 0; j < 8; j++) {
        *(float2*)(p0 + 8*j + 2*t) = make_float2(O[j][0] * inv0, O[j][1] * inv0);
        *(float2*)(p1 + 8*j + 2*t) = make_float2(O[j][2] * inv1, O[j][3] * inv1);
    }
}

// ---------------------------------------------------------------------------
extern "C" void kernel_launch(void* const* d_in, const int* in_sizes, int n_in,
                              void* d_out, int out_size)
{
    const float* x        = (const float*)d_in[0];
    const float* qkv_w    = (const float*)d_in[1];
    const float* qkv_b    = (const float*)d_in[2];
    const float* q_norm_w = (const float*)d_in[3];
    const float* k_norm_w = (const float*)d_in[4];
    const float* proj_w   = (const float*)d_in[5];
    const float* proj_b   = (const float*)d_in[6];
    float* out = (float*)d_out;

    float *wt, *pwt, *go;
    cudaGetSymbolAddress((void**)&wt,  g_wt);
    cudaGetSymbolAddress((void**)&pwt, g_pwt);
    cudaGetSymbolAddress((void**)&go,  g_o);

    cudaFuncSetAttribute(attn_kernel,
                         cudaFuncAttributeMaxDynamicSharedMemorySize, ATTN_SMEM);

    // Weight transposes (N-major -> K-major)
    {
        dim3 tb(32, 8);
        transpose_kernel<<<dim3(QKVN/32, CC/32), tb>>>(qkv_w, wt, CC, QKVN);
        transpose_kernel<<<dim3(CC/32, CC/32), tb>>>(proj_w, pwt, CC, CC);
    }
    // QKV GEMM + bias + fused rmsnorm (HMMA bf16 split)
    {
        dim3 grid(QKVN / 128, MROWS / 128);   // 24 x 32
        hmma_gemm_kernel<<<grid, 256>>>(x, wt, qkv_b, nullptr,
                                        q_norm_w, k_norm_w, 0);
    }
    // Flash attention (HMMA bf16 split)
    {
        dim3 grid(NN / 128, BB * HH);         // 16 x 32
        attn_kernel<<<grid, 256, ATTN_SMEM>>>();
    }
    // Output projection (HMMA bf16 split)
    {
        dim3 grid(CC / 128, MROWS / 128);     // 8 x 32
        hmma_gemm_kernel<<<grid, 256>>>(go, pwt, proj_b, out,
                                        nullptr, nullptr, 1);
    }
}

// round 8
// speedup vs baseline: 2.5552x; 1.1196x over previous
#include <cuda_runtime.h>
#include <cuda_bf16.h>
#include <stdint.h>
#include <math.h>

#define BB 2
#define NN 2048
#define CC 1024
#define HH 16
#define HD 64
#define MROWS (BB*NN)      // 4096
#define QKVN  (3*CC)       // 3072

// Scratch (static device arrays — allowed)
__device__ float g_q[BB*HH*NN*HD];
__device__ float g_k[BB*HH*NN*HD];
__device__ float g_v[BB*HH*NN*HD];
__device__ __nv_bfloat16 g_xh[MROWS*CC],  g_xl[MROWS*CC];    // x hi/lo
__device__ __nv_bfloat16 g_wth[QKVN*CC],  g_wtl[QKVN*CC];    // qkv_w^T hi/lo
__device__ __nv_bfloat16 g_pwth[CC*CC],   g_pwtl[CC*CC];     // proj_w^T hi/lo
__device__ __nv_bfloat16 g_oh[MROWS*CC],  g_ol[MROWS*CC];    // attn out hi/lo

// ---------------------------------------------------------------------------
// helpers
// ---------------------------------------------------------------------------
__device__ __forceinline__ uint32_t smem_to_u32(const void* p) {
    uint32_t a;
    asm("{ .reg .u64 t; cvta.to.shared.u64 t, %1; cvt.u32.u64 %0, t; }"
        : "=r"(a) : "l"(p));
    return a;
}

__device__ __forceinline__ void ldsm4(uint32_t addr, uint32_t* r) {
    asm volatile("ldmatrix.sync.aligned.m8n8.x4.shared.b16 {%0,%1,%2,%3}, [%4];"
                 : "=r"(r[0]), "=r"(r[1]), "=r"(r[2]), "=r"(r[3]) : "r"(addr));
}

__device__ __forceinline__ void mma16816(float* d, const uint32_t* a,
                                         const uint32_t* b) {
    asm volatile(
        "mma.sync.aligned.m16n8k16.row.col.f32.bf16.bf16.f32 "
        "{%0,%1,%2,%3}, {%4,%5,%6,%7}, {%8,%9}, {%0,%1,%2,%3};"
        : "+f"(d[0]), "+f"(d[1]), "+f"(d[2]), "+f"(d[3])
        : "r"(a[0]), "r"(a[1]), "r"(a[2]), "r"(a[3]), "r"(b[0]), "r"(b[1]));
}

__device__ __forceinline__ float ex2(float x) {
    float r; asm("ex2.approx.f32 %0, %1;" : "=f"(r) : "f"(x)); return r;
}

__device__ __forceinline__ void cpa16(uint32_t dst, const void* src) {
    asm volatile("cp.async.cg.shared.global [%0], [%1], 16;" :: "r"(dst), "l"(src));
}
#define CP_COMMIT() asm volatile("cp.async.commit_group;" ::: "memory")
#define CP_WAIT1()  asm volatile("cp.async.wait_group 1;" ::: "memory")

// pack (p0 low, p1 high) as bf16x2; also emit bf16 residual pair
__device__ __forceinline__ void split_pair(float p0, float p1,
                                           uint32_t& hi, uint32_t& lo) {
    __nv_bfloat16 h0 = __float2bfloat16_rn(p0);
    __nv_bfloat16 h1 = __float2bfloat16_rn(p1);
    hi = ((uint32_t)__bfloat16_as_ushort(h1) << 16) | __bfloat16_as_ushort(h0);
    float r0 = p0 - __bfloat162float(h0);
    float r1 = p1 - __bfloat162float(h1);
    asm("cvt.rn.bf16x2.f32 %0, %1, %2;" : "=r"(lo) : "f"(r1), "f"(r0));
}

__device__ __forceinline__ void store_hilo(char* hi, char* lo, uint32_t off, float4 f) {
    uint32_t h01, l01, h23, l23;
    split_pair(f.x, f.y, h01, l01);
    split_pair(f.z, f.w, h23, l23);
    *(uint2*)(hi + off) = make_uint2(h01, h23);
    *(uint2*)(lo + off) = make_uint2(l01, l23);
}

// ---------------------------------------------------------------------------
// x -> bf16 hi/lo (same layout)
// ---------------------------------------------------------------------------
__global__ __launch_bounds__(256)
void convert_x_kernel(const float* __restrict__ x)
{
    const int i = (blockIdx.x * 256 + threadIdx.x) * 4;
    float4 f = *(const float4*)(x + i);
    uint32_t h01, l01, h23, l23;
    split_pair(f.x, f.y, h01, l01);
    split_pair(f.z, f.w, h23, l23);
    *(uint2*)(g_xh + i) = make_uint2(h01, h23);
    *(uint2*)(g_xl + i) = make_uint2(l01, l23);
}

// ---------------------------------------------------------------------------
// Weight transpose+convert: src fp32 [R][C] -> dsth/dstl bf16 [C][R]
// ---------------------------------------------------------------------------
__global__ __launch_bounds__(256)
void transpose_convert_kernel(const float* __restrict__ src,
                              __nv_bfloat16* __restrict__ dsth,
                              __nv_bfloat16* __restrict__ dstl,
                              int R, int C)
{
    __shared__ float t[32][33];
    const int bx = blockIdx.x * 32;   // over C
    const int by = blockIdx.y * 32;   // over R
    const int x = threadIdx.x, y0 = threadIdx.y;
    #pragma unroll
    for (int i = y0; i < 32; i += 8)
        t[i][x] = src[(size_t)(by + i) * C + bx + x];
    __syncthreads();
    #pragma unroll
    for (int i = y0; i < 32; i += 8) {
        float v = t[x][i];
        __nv_bfloat16 h = __float2bfloat16_rn(v);
        dsth[(size_t)(bx + i) * R + by + x] = h;
        dstl[(size_t)(bx + i) * R + by + x] = __float2bfloat16_rn(v - __bfloat162float(h));
    }
}

// ---------------------------------------------------------------------------
// cp.async multistage HMMA GEMM:
// D[128,128] = A[128,K] * B[128,K]^T, A/B pre-split bf16 hi/lo, K-major.
// 256 threads = 8 warps (4 M x 2 N), warp tile 32x64, BK=32, 2 stages.
// Stage (32KB): Ahi @0, Alo @8K, Bhi @16K, Blo @24K, each [128][32] bf16 swz.
// mode 0: QKV epilogue (bias + fused rmsnorm q/k, scatter to g_q/g_k/g_v)
// mode 1: proj epilogue (bias, store fp32 row-major)
// ---------------------------------------------------------------------------
__device__ __forceinline__ uint32_t swz(int row, int kbyte) {   // 64B rows
    return (uint32_t)(row * 64 + ((kbyte & 48) ^ (((row >> 1) & 3) << 4)) + (kbyte & 15));
}

#define GEMM_SMEM 65536

__global__ __launch_bounds__(256, 2)
void hmma_gemm_ca(const __nv_bfloat16* __restrict__ Ah, const __nv_bfloat16* __restrict__ Al,
                  const __nv_bfloat16* __restrict__ Bh, const __nv_bfloat16* __restrict__ Bl,
                  const float* __restrict__ bias, float* __restrict__ out,
                  const float* __restrict__ qnw, const float* __restrict__ knw,
                  int mode)
{
    extern __shared__ __align__(128) char sb[];
    const uint32_t sbu = smem_to_u32(sb);

    const int tid  = threadIdx.x;
    const int lane = tid & 31;
    const int w    = tid >> 5;
    const int wm   = (w >> 1) * 32;
    const int wn   = (w & 1) * 64;
    const int row0 = blockIdx.y * 128;
    const int col0 = blockIdx.x * 128;

    const int amat = lane >> 3;
    const int arow_off = (amat & 1) * 8 + (lane & 7);
    const int akb_off  = (amat >> 1) * 16;
    const int brow_off = (amat >> 1) * 8 + (lane & 7);
    const int bkb_off  = (amat & 1) * 16;

    // chunk mapping: 512 16B-chunks per 8KB buffer; thread does 2 per buffer
    const int ch_row0 = (tid + 0)   >> 2, ch_kc0 = (tid + 0)   & 3;
    const int ch_row1 = (tid + 256) >> 2, ch_kc1 = (tid + 256) & 3;

    auto load_stage = [&](int kt, int slot) {
        const uint32_t base = sbu + (uint32_t)slot * 32768u;
        {
            const uint32_t off = swz(ch_row0, ch_kc0 * 16);
            const size_t as = (size_t)(row0 + ch_row0) * CC + kt * 32 + ch_kc0 * 8;
            const size_t bs = (size_t)(col0 + ch_row0) * CC + kt * 32 + ch_kc0 * 8;
            cpa16(base + off,         Ah + as);
            cpa16(base + 8192 + off,  Al + as);
            cpa16(base + 16384 + off, Bh + bs);
            cpa16(base + 24576 + off, Bl + bs);
        }
        {
            const uint32_t off = swz(ch_row1, ch_kc1 * 16);
            const size_t as = (size_t)(row0 + ch_row1) * CC + kt * 32 + ch_kc1 * 8;
            const size_t bs = (size_t)(col0 + ch_row1) * CC + kt * 32 + ch_kc1 * 8;
            cpa16(base + off,         Ah + as);
            cpa16(base + 8192 + off,  Al + as);
            cpa16(base + 16384 + off, Bh + bs);
            cpa16(base + 24576 + off, Bl + bs);
        }
    };

    float D[2][8][4];
    #pragma unroll
    for (int i = 0; i < 2; i++)
        #pragma unroll
        for (int j = 0; j < 8; j++)
            #pragma unroll
            for (int c = 0; c < 4; c++) D[i][j][c] = 0.f;

    load_stage(0, 0); CP_COMMIT();
    load_stage(1, 1); CP_COMMIT();

    for (int t = 0; t < 32; t++) {
        CP_WAIT1();
        __syncthreads();
        const uint32_t stb = sbu + (uint32_t)(t & 1) * 32768u;

        #pragma unroll
        for (int k16 = 0; k16 < 2; k16++) {
            const int kb = k16 * 32;
            uint32_t a_hi[2][4], a_lo[2][4];
            #pragma unroll
            for (int i = 0; i < 2; i++) {
                const uint32_t aoff = swz(wm + 16*i + arow_off, kb + akb_off);
                ldsm4(stb + aoff, a_hi[i]);
                ldsm4(stb + 8192 + aoff, a_lo[i]);
            }
            #pragma unroll
            for (int j2 = 0; j2 < 4; j2++) {
                const uint32_t boff = swz(wn + j2*16 + brow_off, kb + bkb_off);
                uint32_t b_hi[4], b_lo[4];
                ldsm4(stb + 16384 + boff, b_hi);
                ldsm4(stb + 24576 + boff, b_lo);
                #pragma unroll
                for (int i = 0; i < 2; i++) {
                    mma16816(D[i][2*j2],   a_hi[i], b_hi);
                    mma16816(D[i][2*j2],   a_hi[i], b_lo);
                    mma16816(D[i][2*j2],   a_lo[i], b_hi);
                    mma16816(D[i][2*j2+1], a_hi[i], b_hi + 2);
                    mma16816(D[i][2*j2+1], a_hi[i], b_lo + 2);
                    mma16816(D[i][2*j2+1], a_lo[i], b_hi + 2);
                }
            }
        }
        __syncthreads();
        if (t + 2 < 32) { load_stage(t + 2, t & 1); CP_COMMIT(); }
    }

    // ---- Epilogue (validated in rounds 6-7) ----
    const int g = lane >> 2;
    const int t4 = lane & 3;
    const int colw = col0 + wn;
    const int s   = (mode == 0) ? (colw >> 10) : 3;
    const int h   = (colw & 1023) >> 6;
    float* dst = (mode == 0) ? ((s == 0) ? g_q : (s == 1) ? g_k : g_v) : out;
    const float* nw = (s == 0) ? qnw : knw;
    const float postscale = (s == 0) ? 0.18033688011112042f : 1.0f; // 0.125*log2(e)

    #pragma unroll
    for (int i = 0; i < 2; i++) {
        float v0[16], v1[16];
        #pragma unroll
        for (int j = 0; j < 8; j++) {
            const float bj0 = bias[colw + 8*j + 2*t4];
            const float bj1 = bias[colw + 8*j + 2*t4 + 1];
            v0[2*j]   = D[i][j][0] + bj0;
            v0[2*j+1] = D[i][j][1] + bj1;
            v1[2*j]   = D[i][j][2] + bj0;
            v1[2*j+1] = D[i][j][3] + bj1;
        }
        if (mode == 0 && s < 2) {
            float ss0 = 0.f, ss1 = 0.f;
            #pragma unroll
            for (int c = 0; c < 16; c++) { ss0 += v0[c]*v0[c]; ss1 += v1[c]*v1[c]; }
            ss0 += __shfl_xor_sync(0xffffffffu, ss0, 1);
            ss0 += __shfl_xor_sync(0xffffffffu, ss0, 2);
            ss1 += __shfl_xor_sync(0xffffffffu, ss1, 1);
            ss1 += __shfl_xor_sync(0xffffffffu, ss1, 2);
            const float n0 = rsqrtf(ss0 * (1.0f/64.0f) + 1e-6f) * postscale;
            const float n1 = rsqrtf(ss1 * (1.0f/64.0f) + 1e-6f) * postscale;
            #pragma unroll
            for (int j = 0; j < 8; j++) {
                const float w0 = nw[8*j + 2*t4], w1 = nw[8*j + 2*t4 + 1];
                v0[2*j]   *= n0 * w0;  v0[2*j+1] *= n0 * w1;
                v1[2*j]   *= n1 * w0;  v1[2*j+1] *= n1 * w1;
            }
        }
        const int gr0 = row0 + wm + 16*i + g;
        const int gr1 = gr0 + 8;
        if (mode == 0) {
            const int b0r = gr0 >> 11, n0r = gr0 & 2047;
            const int b1r = gr1 >> 11, n1r = gr1 & 2047;
            float* p0 = dst + (((size_t)(b0r * HH + h) * NN) + n0r) * HD;
            float* p1 = dst + (((size_t)(b1r * HH + h) * NN) + n1r) * HD;
            #pragma unroll
            for (int j = 0; j < 8; j++) {
                *(float2*)(p0 + 8*j + 2*t4) = make_float2(v0[2*j], v0[2*j+1]);
                *(float2*)(p1 + 8*j + 2*t4) = make_float2(v1[2*j], v1[2*j+1]);
            }
        } else {
            float* p0 = out + (size_t)gr0 * CC + colw;
            float* p1 = out + (size_t)gr1 * CC + colw;
            #pragma unroll
            for (int j = 0; j < 8; j++) {
                *(float2*)(p0 + 8*j + 2*t4) = make_float2(v0[2*j], v0[2*j+1]);
                *(float2*)(p1 + 8*j + 2*t4) = make_float2(v1[2*j], v1[2*j+1]);
            }
        }
    }
}

// ---------------------------------------------------------------------------
// HMMA flash attention, 64-q blocks (128 threads, 4 warps x 16 q-rows),
// 2 blocks/SM. SMEM 80KB: Q[64][64]@0/8K, K[128][64]@16K/32K,
// Vt[64][128]@48K/64K (hi/lo bf16, swizzled).
// Output written directly as bf16 hi/lo (g_oh/g_ol) for the proj GEMM.
// ---------------------------------------------------------------------------
__device__ __forceinline__ uint32_t swz_qk(int row, int kbyte) {   // 128B rows
    return (uint32_t)(row * 128 + ((((kbyte >> 4) ^ row) & 7) << 4) + (kbyte & 15));
}
__device__ __forceinline__ uint32_t swz_v(int row, int kbyte) {    // 256B rows
    return (uint32_t)(row * 256 + (kbyte & 128) +
                      ((((kbyte >> 4) ^ row) & 7) << 4) + (kbyte & 15));
}

#define ATTN_SMEM 81920

__global__ __launch_bounds__(128, 2)
void attn_kernel()
{
    extern __shared__ __align__(128) char smem[];
    char* Qhi  = smem;            // 8K
    char* Qlo  = smem + 8192;
    char* Khi  = smem + 16384;    // 16K
    char* Klo  = smem + 32768;
    char* Vthi = smem + 49152;    // 16K
    char* Vtlo = smem + 65536;
    const uint32_t sbu = smem_to_u32(smem);

    const int tid  = threadIdx.x;
    const int lane = tid & 31;
    const int w    = tid >> 5;     // 0..3
    const int wm   = w * 16;
    const int g = lane >> 2, t = lane & 3;

    const int bh = blockIdx.y;
    const int b  = bh >> 4, h = bh & 15;
    const int qt = blockIdx.x;     // 0..31 (64-q tiles)

    const float* qbase = g_q + ((size_t)bh * NN + qt * 64) * HD;
    const float* kbase = g_k + (size_t)bh * NN * HD;
    const float* vbase = g_v + (size_t)bh * NN * HD;

    const int amat = lane >> 3;
    const int arow_off = (amat & 1) * 8 + (lane & 7);
    const int akb_off  = (amat >> 1) * 16;
    const int brow_off = (amat >> 1) * 8 + (lane & 7);
    const int bkb_off  = (amat & 1) * 16;

    // ---- load Q tile (64 rows) ----
    {
        const int row = tid >> 1;
        const int kh  = (tid & 1) * 32;
        const float* qp = qbase + (size_t)row * HD + kh;
        #pragma unroll
        for (int c = 0; c < 8; c++) {
            float4 f = *(const float4*)(qp + c*4);
            store_hilo(Qhi, Qlo, swz_qk(row, (kh + c*4) * 2), f);
        }
    }
    __syncthreads();

    // ---- Q fragments (16 rows x 64 hd) ----
    uint32_t qh[4][4], ql[4][4];
    #pragma unroll
    for (int kk = 0; kk < 4; kk++) {
        const uint32_t off = swz_qk(wm + arow_off, kk*32 + akb_off);
        ldsm4(sbu + off, qh[kk]);
        ldsm4(sbu + 8192 + off, ql[kk]);
    }

    float m0 = -1e30f, m1 = -1e30f, l0 = 0.f, l1 = 0.f;
    float O[8][4];
    #pragma unroll
    for (int j = 0; j < 8; j++)
        #pragma unroll
        for (int c = 0; c < 4; c++) O[j][c] = 0.f;

    for (int kt = 0; kt < NN / 128; kt++) {
        // ---- load K tile [128][64]: one row per thread ----
        {
            const float* kp = kbase + (size_t)(kt * 128 + tid) * HD;
            #pragma unroll
            for (int c = 0; c < 16; c++) {
                float4 f = *(const float4*)(kp + c*4);
                store_hilo(Khi, Klo, swz_qk(tid, c*8), f);
            }
        }
        // ---- load V tile transposed -> Vt [64][128] ----
        {
            const int hd = tid & 63;
            const int kg = tid >> 6;    // 0..1
            #pragma unroll
            for (int ii = 0; ii < 16; ii++) {
                const int k0 = kg * 64 + ii * 4;
                const float* vp = vbase + (size_t)(kt * 128 + k0) * HD + hd;
                float f0 = vp[0], f1 = vp[64], f2 = vp[128], f3 = vp[192];
                uint32_t h01, l01, h23, l23;
                split_pair(f0, f1, h01, l01);
                split_pair(f2, f3, h23, l23);
                const uint32_t off = swz_v(hd, k0 * 2);
                *(uint2*)(Vthi + off) = make_uint2(h01, h23);
                *(uint2*)(Vtlo + off) = make_uint2(l01, l23);
            }
        }
        __syncthreads();

        // ---- S = Q K^T ----
        float S[16][4];
        #pragma unroll
        for (int j = 0; j < 16; j++)
            #pragma unroll
            for (int c = 0; c < 4; c++) S[j][c] = 0.f;

        #pragma unroll
        for (int kk = 0; kk < 4; kk++) {
            #pragma unroll
            for (int j2 = 0; j2 < 8; j2++) {
                const uint32_t off = swz_qk(j2*16 + brow_off, kk*32 + bkb_off);
                uint32_t bhh[4], bll[4];
                ldsm4(sbu + 16384 + off, bhh);
                ldsm4(sbu + 32768 + off, bll);
                mma16816(S[2*j2],   qh[kk], bhh);
                mma16816(S[2*j2],   qh[kk], bll);
                mma16816(S[2*j2],   ql[kk], bhh);
                mma16816(S[2*j2+1], qh[kk], bhh + 2);
                mma16816(S[2*j2+1], qh[kk], bll + 2);
                mma16816(S[2*j2+1], ql[kk], bhh + 2);
            }
        }

        // ---- online softmax (base-2 domain) ----
        float mx0 = S[0][0], mx1 = S[0][2];
        #pragma unroll
        for (int j = 0; j < 16; j++) {
            mx0 = fmaxf(mx0, fmaxf(S[j][0], S[j][1]));
            mx1 = fmaxf(mx1, fmaxf(S[j][2], S[j][3]));
        }
        mx0 = fmaxf(mx0, __shfl_xor_sync(0xffffffffu, mx0, 1));
        mx0 = fmaxf(mx0, __shfl_xor_sync(0xffffffffu, mx0, 2));
        mx1 = fmaxf(mx1, __shfl_xor_sync(0xffffffffu, mx1, 1));
        mx1 = fmaxf(mx1, __shfl_xor_sync(0xffffffffu, mx1, 2));
        const float mn0 = fmaxf(m0, mx0);
        const float mn1 = fmaxf(m1, mx1);
        const float c0 = ex2(m0 - mn0);
        const float c1 = ex2(m1 - mn1);
        m0 = mn0; m1 = mn1;

        float sum0 = 0.f, sum1 = 0.f;
        #pragma unroll
        for (int j = 0; j < 16; j++) {
            S[j][0] = ex2(S[j][0] - mn0); sum0 += S[j][0];
            S[j][1] = ex2(S[j][1] - mn0); sum0 += S[j][1];
            S[j][2] = ex2(S[j][2] - mn1); sum1 += S[j][2];
            S[j][3] = ex2(S[j][3] - mn1); sum1 += S[j][3];
        }
        sum0 += __shfl_xor_sync(0xffffffffu, sum0, 1);
        sum0 += __shfl_xor_sync(0xffffffffu, sum0, 2);
        sum1 += __shfl_xor_sync(0xffffffffu, sum1, 1);
        sum1 += __shfl_xor_sync(0xffffffffu, sum1, 2);
        l0 = l0 * c0 + sum0;
        l1 = l1 * c1 + sum1;

        #pragma unroll
        for (int j = 0; j < 8; j++) {
            O[j][0] *= c0; O[j][1] *= c0;
            O[j][2] *= c1; O[j][3] *= c1;
        }

        // ---- O += P V (P from S fragments in registers) ----
        #pragma unroll
        for (int kk = 0; kk < 8; kk++) {
            uint32_t phi[4], plo[4];
            split_pair(S[2*kk][0],   S[2*kk][1],   phi[0], plo[0]);
            split_pair(S[2*kk][2],   S[2*kk][3],   phi[1], plo[1]);
            split_pair(S[2*kk+1][0], S[2*kk+1][1], phi[2], plo[2]);
            split_pair(S[2*kk+1][2], S[2*kk+1][3], phi[3], plo[3]);
            #pragma unroll
            for (int jh = 0; jh < 4; jh++) {
                const uint32_t off = swz_v(jh*16 + brow_off, kk*32 + bkb_off);
                uint32_t vh[4], vl[4];
                ldsm4(sbu + 49152 + off, vh);
                ldsm4(sbu + 65536 + off, vl);
                mma16816(O[2*jh],   phi, vh);
                mma16816(O[2*jh],   phi, vl);
                mma16816(O[2*jh],   plo, vh);
                mma16816(O[2*jh+1], phi, vh + 2);
                mma16816(O[2*jh+1], phi, vl + 2);
                mma16816(O[2*jh+1], plo, vh + 2);
            }
        }
        __syncthreads();   // PV done before next tile's loads overwrite K/Vt
    }

    // ---- epilogue: normalize, write bf16 hi/lo to g_oh/g_ol [B,N,C] ----
    const float inv0 = 1.0f / l0;
    const float inv1 = 1.0f / l1;
    const int q0 = qt * 64 + wm + g;
    const size_t p0 = ((size_t)b * NN + q0) * CC + h * HD;
    const size_t p1 = ((size_t)b * NN + q0 + 8) * CC + h * HD;
    #pragma unroll
    for (int j = 0; j < 8; j++) {
        uint32_t hi, lo;
        split_pair(O[j][0] * inv0, O[j][1] * inv0, hi, lo);
        *(uint32_t*)(g_oh + p0 + 8*j + 2*t) = hi;
        *(uint32_t*)(g_ol + p0 + 8*j + 2*t) = lo;
        split_pair(O[j][2] * inv1, O[j][3] * inv1, hi, lo);
        *(uint32_t*)(g_oh + p1 + 8*j + 2*t) = hi;
        *(uint32_t*)(g_ol + p1 + 8*j + 2*t) = lo;
    }
}

// ---------------------------------------------------------------------------
extern "C" void kernel_launch(void* const* d_in, const int* in_sizes, int n_in,
                              void* d_out, int out_size)
{
    const float* x        = (const float*)d_in[0];
    const float* qkv_w    = (const float*)d_in[1];
    const float* qkv_b    = (const float*)d_in[2];
    const float* q_norm_w = (const float*)d_in[3];
    const float* k_norm_w = (const float*)d_in[4];
    const float* proj_w   = (const float*)d_in[5];
    const float* proj_b   = (const float*)d_in[6];
    float* out = (float*)d_out;

    __nv_bfloat16 *xh, *xl, *wth, *wtl, *pwth, *pwtl, *oh, *ol;
    cudaGetSymbolAddress((void**)&xh,   g_xh);
    cudaGetSymbolAddress((void**)&xl,   g_xl);
    cudaGetSymbolAddress((void**)&wth,  g_wth);
    cudaGetSymbolAddress((void**)&wtl,  g_wtl);
    cudaGetSymbolAddress((void**)&pwth, g_pwth);
    cudaGetSymbolAddress((void**)&pwtl, g_pwtl);
    cudaGetSymbolAddress((void**)&oh,   g_oh);
    cudaGetSymbolAddress((void**)&ol,   g_ol);

    cudaFuncSetAttribute(hmma_gemm_ca,
                         cudaFuncAttributeMaxDynamicSharedMemorySize, GEMM_SMEM);
    cudaFuncSetAttribute(attn_kernel,
                         cudaFuncAttributeMaxDynamicSharedMemorySize, ATTN_SMEM);

    // Operand conversion (x elementwise; weights transpose+convert)
    convert_x_kernel<<<MROWS * CC / 1024, 256>>>(x);
    {
        dim3 tb(32, 8);
        transpose_convert_kernel<<<dim3(QKVN/32, CC/32), tb>>>(qkv_w, wth, wtl, CC, QKVN);
        transpose_convert_kernel<<<dim3(CC/32, CC/32), tb>>>(proj_w, pwth, pwtl, CC, CC);
    }
    // QKV GEMM + bias + fused rmsnorm
    {
        dim3 grid(QKVN / 128, MROWS / 128);   // 24 x 32
        hmma_gemm_ca<<<grid, 256, GEMM_SMEM>>>(xh, xl, wth, wtl, qkv_b, nullptr,
                                               q_norm_w, k_norm_w, 0);
    }
    // Flash attention (HMMA, 64-q blocks)
    {
        dim3 grid(NN / 64, BB * HH);          // 32 x 32
        attn_kernel<<<grid, 128, ATTN_SMEM>>>();
    }
    // Output projection
    {
        dim3 grid(CC / 128, MROWS / 128);     // 8 x 32
        hmma_gemm_ca<<<grid, 256, GEMM_SMEM>>>(oh, ol, pwth, pwtl, proj_b, out,
                                               nullptr, nullptr, 1);
    }
}

// round 9
// speedup vs baseline: 3.4258x; 1.3408x over previous
#include <cuda_runtime.h>
#include <cuda_bf16.h>
#include <stdint.h>
#include <math.h>

#define BB 2
#define NN 2048
#define CC 1024
#define HH 16
#define HD 64
#define MROWS (BB*NN)      // 4096
#define QKVN  (3*CC)       // 3072
#define QKV_ELEMS (BB*HH*NN*HD)   // 4194304

// Scratch (static device arrays — allowed)
__device__ __nv_bfloat16 g_qh[QKV_ELEMS], g_ql[QKV_ELEMS];   // q  [B,H,N,hd]
__device__ __nv_bfloat16 g_kh[QKV_ELEMS], g_kl[QKV_ELEMS];   // k  [B,H,N,hd]
__device__ __nv_bfloat16 g_vh[QKV_ELEMS], g_vl[QKV_ELEMS];   // v  [B,H,N,hd]
__device__ __nv_bfloat16 g_vth[QKV_ELEMS], g_vtl[QKV_ELEMS]; // v^T [B,H,hd,N]
__device__ __nv_bfloat16 g_xh[MROWS*CC],  g_xl[MROWS*CC];    // x hi/lo
__device__ __nv_bfloat16 g_wth[QKVN*CC],  g_wtl[QKVN*CC];    // qkv_w^T hi/lo
__device__ __nv_bfloat16 g_pwth[CC*CC],   g_pwtl[CC*CC];     // proj_w^T hi/lo
__device__ __nv_bfloat16 g_oh[MROWS*CC],  g_ol[MROWS*CC];    // attn out hi/lo

// ---------------------------------------------------------------------------
// helpers
// ---------------------------------------------------------------------------
__device__ __forceinline__ uint32_t smem_to_u32(const void* p) {
    uint32_t a;
    asm("{ .reg .u64 t; cvta.to.shared.u64 t, %1; cvt.u32.u64 %0, t; }"
        : "=r"(a) : "l"(p));
    return a;
}

__device__ __forceinline__ void ldsm4(uint32_t addr, uint32_t* r) {
    asm volatile("ldmatrix.sync.aligned.m8n8.x4.shared.b16 {%0,%1,%2,%3}, [%4];"
                 : "=r"(r[0]), "=r"(r[1]), "=r"(r[2]), "=r"(r[3]) : "r"(addr));
}

__device__ __forceinline__ void mma16816(float* d, const uint32_t* a,
                                         const uint32_t* b) {
    asm volatile(
        "mma.sync.aligned.m16n8k16.row.col.f32.bf16.bf16.f32 "
        "{%0,%1,%2,%3}, {%4,%5,%6,%7}, {%8,%9}, {%0,%1,%2,%3};"
        : "+f"(d[0]), "+f"(d[1]), "+f"(d[2]), "+f"(d[3])
        : "r"(a[0]), "r"(a[1]), "r"(a[2]), "r"(a[3]), "r"(b[0]), "r"(b[1]));
}

__device__ __forceinline__ float ex2(float x) {
    float r; asm("ex2.approx.f32 %0, %1;" : "=f"(r) : "f"(x)); return r;
}

__device__ __forceinline__ void cpa16(uint32_t dst, const void* src) {
    asm volatile("cp.async.cg.shared.global [%0], [%1], 16;" :: "r"(dst), "l"(src));
}
#define CP_COMMIT() asm volatile("cp.async.commit_group;" ::: "memory")
#define CP_WAIT1()  asm volatile("cp.async.wait_group 1;" ::: "memory")

// pack (p0 low, p1 high) as bf16x2; also emit bf16 residual pair
__device__ __forceinline__ void split_pair(float p0, float p1,
                                           uint32_t& hi, uint32_t& lo) {
    __nv_bfloat16 h0 = __float2bfloat16_rn(p0);
    __nv_bfloat16 h1 = __float2bfloat16_rn(p1);
    hi = ((uint32_t)__bfloat16_as_ushort(h1) << 16) | __bfloat16_as_ushort(h0);
    float r0 = p0 - __bfloat162float(h0);
    float r1 = p1 - __bfloat162float(h1);
    asm("cvt.rn.bf16x2.f32 %0, %1, %2;" : "=r"(lo) : "f"(r1), "f"(r0));
}

// ---------------------------------------------------------------------------
// x -> bf16 hi/lo (same layout)
// ---------------------------------------------------------------------------
__global__ __launch_bounds__(256)
void convert_x_kernel(const float* __restrict__ x)
{
    const int i = (blockIdx.x * 256 + threadIdx.x) * 4;
    float4 f = *(const float4*)(x + i);
    uint32_t h01, l01, h23, l23;
    split_pair(f.x, f.y, h01, l01);
    split_pair(f.z, f.w, h23, l23);
    *(uint2*)(g_xh + i) = make_uint2(h01, h23);
    *(uint2*)(g_xl + i) = make_uint2(l01, l23);
}

// ---------------------------------------------------------------------------
// Weight transpose+convert: src fp32 [R][C] -> dsth/dstl bf16 [C][R]
// ---------------------------------------------------------------------------
__global__ __launch_bounds__(256)
void transpose_convert_kernel(const float* __restrict__ src,
                              __nv_bfloat16* __restrict__ dsth,
                              __nv_bfloat16* __restrict__ dstl,
                              int R, int C)
{
    __shared__ float t[32][33];
    const int bx = blockIdx.x * 32;   // over C
    const int by = blockIdx.y * 32;   // over R
    const int x = threadIdx.x, y0 = threadIdx.y;
    #pragma unroll
    for (int i = y0; i < 32; i += 8)
        t[i][x] = src[(size_t)(by + i) * C + bx + x];
    __syncthreads();
    #pragma unroll
    for (int i = y0; i < 32; i += 8) {
        float v = t[x][i];
        __nv_bfloat16 h = __float2bfloat16_rn(v);
        dsth[(size_t)(bx + i) * R + by + x] = h;
        dstl[(size_t)(bx + i) * R + by + x] = __float2bfloat16_rn(v - __bfloat162float(h));
    }
}

// ---------------------------------------------------------------------------
// v transpose (bf16): per (b,h): [NN][HD] -> [HD][NN], both hi and lo
// ---------------------------------------------------------------------------
__global__ __launch_bounds__(256)
void transpose_v_kernel()
{
    __shared__ ushort th[32][33];
    __shared__ ushort tl[32][33];
    const int bh = blockIdx.z;
    const int by = blockIdx.x * 32;    // over N
    const int bx = blockIdx.y * 32;    // over hd
    const int x = threadIdx.x, y0 = threadIdx.y;
    const size_t sbase = (size_t)bh * NN * HD;
    #pragma unroll
    for (int i = y0; i < 32; i += 8) {
        th[i][x] = __bfloat16_as_ushort(g_vh[sbase + (size_t)(by + i) * HD + bx + x]);
        tl[i][x] = __bfloat16_as_ushort(g_vl[sbase + (size_t)(by + i) * HD + bx + x]);
    }
    __syncthreads();
    #pragma unroll
    for (int i = y0; i < 32; i += 8) {
        g_vth[sbase + (size_t)(bx + i) * NN + by + x] = __ushort_as_bfloat16(th[x][i]);
        g_vtl[sbase + (size_t)(bx + i) * NN + by + x] = __ushort_as_bfloat16(tl[x][i]);
    }
}

// ---------------------------------------------------------------------------
// cp.async multistage HMMA GEMM (validated round 8):
// mode 0: QKV epilogue -> bias + fused rmsnorm q/k -> bf16 hi/lo scatter
// mode 1: proj epilogue -> bias -> fp32 row-major out
// ---------------------------------------------------------------------------
__device__ __forceinline__ uint32_t swz(int row, int kbyte) {   // 64B rows
    return (uint32_t)(row * 64 + ((kbyte & 48) ^ (((row >> 1) & 3) << 4)) + (kbyte & 15));
}

#define GEMM_SMEM 65536

__global__ __launch_bounds__(256, 2)
void hmma_gemm_ca(const __nv_bfloat16* __restrict__ Ah, const __nv_bfloat16* __restrict__ Al,
                  const __nv_bfloat16* __restrict__ Bh, const __nv_bfloat16* __restrict__ Bl,
                  const float* __restrict__ bias, float* __restrict__ out,
                  const float* __restrict__ qnw, const float* __restrict__ knw,
                  int mode)
{
    extern __shared__ __align__(128) char sb[];
    const uint32_t sbu = smem_to_u32(sb);

    const int tid  = threadIdx.x;
    const int lane = tid & 31;
    const int w    = tid >> 5;
    const int wm   = (w >> 1) * 32;
    const int wn   = (w & 1) * 64;
    const int row0 = blockIdx.y * 128;
    const int col0 = blockIdx.x * 128;

    const int amat = lane >> 3;
    const int arow_off = (amat & 1) * 8 + (lane & 7);
    const int akb_off  = (amat >> 1) * 16;
    const int brow_off = (amat >> 1) * 8 + (lane & 7);
    const int bkb_off  = (amat & 1) * 16;

    const int ch_row0 = (tid + 0)   >> 2, ch_kc0 = (tid + 0)   & 3;
    const int ch_row1 = (tid + 256) >> 2, ch_kc1 = (tid + 256) & 3;

    auto load_stage = [&](int kt, int slot) {
        const uint32_t base = sbu + (uint32_t)slot * 32768u;
        {
            const uint32_t off = swz(ch_row0, ch_kc0 * 16);
            const size_t as = (size_t)(row0 + ch_row0) * CC + kt * 32 + ch_kc0 * 8;
            const size_t bs = (size_t)(col0 + ch_row0) * CC + kt * 32 + ch_kc0 * 8;
            cpa16(base + off,         Ah + as);
            cpa16(base + 8192 + off,  Al + as);
            cpa16(base + 16384 + off, Bh + bs);
            cpa16(base + 24576 + off, Bl + bs);
        }
        {
            const uint32_t off = swz(ch_row1, ch_kc1 * 16);
            const size_t as = (size_t)(row0 + ch_row1) * CC + kt * 32 + ch_kc1 * 8;
            const size_t bs = (size_t)(col0 + ch_row1) * CC + kt * 32 + ch_kc1 * 8;
            cpa16(base + off,         Ah + as);
            cpa16(base + 8192 + off,  Al + as);
            cpa16(base + 16384 + off, Bh + bs);
            cpa16(base + 24576 + off, Bl + bs);
        }
    };

    float D[2][8][4];
    #pragma unroll
    for (int i = 0; i < 2; i++)
        #pragma unroll
        for (int j = 0; j < 8; j++)
            #pragma unroll
            for (int c = 0; c < 4; c++) D[i][j][c] = 0.f;

    load_stage(0, 0); CP_COMMIT();
    load_stage(1, 1); CP_COMMIT();

    for (int t = 0; t < 32; t++) {
        CP_WAIT1();
        __syncthreads();
        const uint32_t stb = sbu + (uint32_t)(t & 1) * 32768u;

        #pragma unroll
        for (int k16 = 0; k16 < 2; k16++) {
            const int kb = k16 * 32;
            uint32_t a_hi[2][4], a_lo[2][4];
            #pragma unroll
            for (int i = 0; i < 2; i++) {
                const uint32_t aoff = swz(wm + 16*i + arow_off, kb + akb_off);
                ldsm4(stb + aoff, a_hi[i]);
                ldsm4(stb + 8192 + aoff, a_lo[i]);
            }
            #pragma unroll
            for (int j2 = 0; j2 < 4; j2++) {
                const uint32_t boff = swz(wn + j2*16 + brow_off, kb + bkb_off);
                uint32_t b_hi[4], b_lo[4];
                ldsm4(stb + 16384 + boff, b_hi);
                ldsm4(stb + 24576 + boff, b_lo);
                #pragma unroll
                for (int i = 0; i < 2; i++) {
                    mma16816(D[i][2*j2],   a_hi[i], b_hi);
                    mma16816(D[i][2*j2],   a_hi[i], b_lo);
                    mma16816(D[i][2*j2],   a_lo[i], b_hi);
                    mma16816(D[i][2*j2+1], a_hi[i], b_hi + 2);
                    mma16816(D[i][2*j2+1], a_hi[i], b_lo + 2);
                    mma16816(D[i][2*j2+1], a_lo[i], b_hi + 2);
                }
            }
        }
        __syncthreads();
        if (t + 2 < 32) { load_stage(t + 2, t & 1); CP_COMMIT(); }
    }

    // ---- Epilogue ----
    const int g = lane >> 2;
    const int t4 = lane & 3;
    const int colw = col0 + wn;
    const int s   = (mode == 0) ? (colw >> 10) : 3;
    const int h   = (colw & 1023) >> 6;
    const float* nw = (s == 0) ? qnw : knw;
    const float postscale = (s == 0) ? 0.18033688011112042f : 1.0f; // 0.125*log2(e)
    __nv_bfloat16* dsth = (s == 0) ? g_qh : (s == 1) ? g_kh : g_vh;
    __nv_bfloat16* dstl = (s == 0) ? g_ql : (s == 1) ? g_kl : g_vl;

    #pragma unroll
    for (int i = 0; i < 2; i++) {
        float v0[16], v1[16];
        #pragma unroll
        for (int j = 0; j < 8; j++) {
            const float bj0 = bias[colw + 8*j + 2*t4];
            const float bj1 = bias[colw + 8*j + 2*t4 + 1];
            v0[2*j]   = D[i][j][0] + bj0;
            v0[2*j+1] = D[i][j][1] + bj1;
            v1[2*j]   = D[i][j][2] + bj0;
            v1[2*j+1] = D[i][j][3] + bj1;
        }
        if (mode == 0 && s < 2) {
            float ss0 = 0.f, ss1 = 0.f;
            #pragma unroll
            for (int c = 0; c < 16; c++) { ss0 += v0[c]*v0[c]; ss1 += v1[c]*v1[c]; }
            ss0 += __shfl_xor_sync(0xffffffffu, ss0, 1);
            ss0 += __shfl_xor_sync(0xffffffffu, ss0, 2);
            ss1 += __shfl_xor_sync(0xffffffffu, ss1, 1);
            ss1 += __shfl_xor_sync(0xffffffffu, ss1, 2);
            const float n0 = rsqrtf(ss0 * (1.0f/64.0f) + 1e-6f) * postscale;
            const float n1 = rsqrtf(ss1 * (1.0f/64.0f) + 1e-6f) * postscale;
            #pragma unroll
            for (int j = 0; j < 8; j++) {
                const float w0 = nw[8*j + 2*t4], w1 = nw[8*j + 2*t4 + 1];
                v0[2*j]   *= n0 * w0;  v0[2*j+1] *= n0 * w1;
                v1[2*j]   *= n1 * w0;  v1[2*j+1] *= n1 * w1;
            }
        }
        const int gr0 = row0 + wm + 16*i + g;
        const int gr1 = gr0 + 8;
        if (mode == 0) {
            const int b0r = gr0 >> 11, n0r = gr0 & 2047;
            const int b1r = gr1 >> 11, n1r = gr1 & 2047;
            const size_t p0 = (((size_t)(b0r * HH + h) * NN) + n0r) * HD;
            const size_t p1 = (((size_t)(b1r * HH + h) * NN) + n1r) * HD;
            #pragma unroll
            for (int j = 0; j < 8; j++) {
                uint32_t hi, lo;
                split_pair(v0[2*j], v0[2*j+1], hi, lo);
                *(uint32_t*)(dsth + p0 + 8*j + 2*t4) = hi;
                *(uint32_t*)(dstl + p0 + 8*j + 2*t4) = lo;
                split_pair(v1[2*j], v1[2*j+1], hi, lo);
                *(uint32_t*)(dsth + p1 + 8*j + 2*t4) = hi;
                *(uint32_t*)(dstl + p1 + 8*j + 2*t4) = lo;
            }
        } else {
            float* p0 = out + (size_t)gr0 * CC + colw;
            float* p1 = out + (size_t)gr1 * CC + colw;
            #pragma unroll
            for (int j = 0; j < 8; j++) {
                *(float2*)(p0 + 8*j + 2*t4) = make_float2(v0[2*j], v0[2*j+1]);
                *(float2*)(p1 + 8*j + 2*t4) = make_float2(v1[2*j], v1[2*j+1]);
            }
        }
    }
}

// ---------------------------------------------------------------------------
// HMMA flash attention, all-bf16 inputs + cp.async double buffering.
// Block = 64 q-rows x (b,h); 128 threads (4 warps x 16 q-rows); 2 blocks/SM.
// SMEM 80KB: Q hi/lo [64][64] @0/8K; stage s @16K+s*32K:
//   Khi/Klo [64][64] @+0/+8K, Vthi/Vtlo [64 d][64 k] @+16K/+24K.
// All tiles 128B rows -> swz_qk. 64-key tiles, 32 iterations.
// ---------------------------------------------------------------------------
__device__ __forceinline__ uint32_t swz_qk(int row, int kbyte) {   // 128B rows
    return (uint32_t)(row * 128 + ((((kbyte >> 4) ^ row) & 7) << 4) + (kbyte & 15));
}

#define ATTN_SMEM 81920

__global__ __launch_bounds__(128, 2)
void attn_kernel()
{
    extern __shared__ __align__(128) char smem[];
    const uint32_t sbu = smem_to_u32(smem);

    const int tid  = threadIdx.x;
    const int lane = tid & 31;
    const int w    = tid >> 5;     // 0..3
    const int wm   = w * 16;
    const int g = lane >> 2, t = lane & 3;

    const int bh = blockIdx.y;
    const int b  = bh >> 4, h = bh & 15;
    const int qt = blockIdx.x;     // 0..31

    const size_t qoff  = ((size_t)bh * NN + qt * 64) * HD;
    const size_t kbase = (size_t)bh * NN * HD;
    const size_t vtbase = (size_t)bh * HD * NN;

    const int amat = lane >> 3;
    const int arow_off = (amat & 1) * 8 + (lane & 7);
    const int akb_off  = (amat >> 1) * 16;
    const int brow_off = (amat >> 1) * 8 + (lane & 7);
    const int bkb_off  = (amat & 1) * 16;

    // ---- stage loader: K + Vt, 64-key tile, 4 chunks/thread/buffer ----
    auto load_stage = [&](int kt, int slot) {
        const uint32_t base = sbu + 16384u + (uint32_t)slot * 32768u;
        #pragma unroll
        for (int c = 0; c < 4; c++) {
            const int idx = tid + 128 * c;
            const int row = idx >> 3;
            const int kc  = idx & 7;
            const uint32_t off = swz_qk(row, kc * 16);
            const size_t ks = kbase + (size_t)(kt * 64 + row) * HD + kc * 8;
            const size_t vs = vtbase + (size_t)row * NN + kt * 64 + kc * 8;
            cpa16(base + off,          g_kh + ks);
            cpa16(base + 8192 + off,   g_kl + ks);
            cpa16(base + 16384 + off,  g_vth + vs);
            cpa16(base + 24576 + off,  g_vtl + vs);
        }
    };

    load_stage(0, 0); CP_COMMIT();
    load_stage(1, 1); CP_COMMIT();

    // ---- load Q tile (plain 16B copies; 4 chunks/thread/buffer) ----
    #pragma unroll
    for (int c = 0; c < 4; c++) {
        const int idx = tid + 128 * c;
        const int row = idx >> 3;
        const int kc  = idx & 7;
        const uint32_t off = swz_qk(row, kc * 16);
        *(uint4*)(smem + off)        = *(const uint4*)(g_qh + qoff + (size_t)row * HD + kc * 8);
        *(uint4*)(smem + 8192 + off) = *(const uint4*)(g_ql + qoff + (size_t)row * HD + kc * 8);
    }
    __syncthreads();

    // ---- Q fragments (16 rows x 64 hd) ----
    uint32_t qh[4][4], ql[4][4];
    #pragma unroll
    for (int kk = 0; kk < 4; kk++) {
        const uint32_t off = swz_qk(wm + arow_off, kk*32 + akb_off);
        ldsm4(sbu + off, qh[kk]);
        ldsm4(sbu + 8192 + off, ql[kk]);
    }

    float m0 = -1e30f, m1 = -1e30f, l0 = 0.f, l1 = 0.f;
    float O[8][4];
    #pragma unroll
    for (int j = 0; j < 8; j++)
        #pragma unroll
        for (int c = 0; c < 4; c++) O[j][c] = 0.f;

    for (int kt = 0; kt < NN / 64; kt++) {
        CP_WAIT1();
        __syncthreads();
        const uint32_t stb = sbu + 16384u + (uint32_t)(kt & 1) * 32768u;

        // ---- S = Q K^T (64 keys) ----
        float S[8][4];
        #pragma unroll
        for (int j = 0; j < 8; j++)
            #pragma unroll
            for (int c = 0; c < 4; c++) S[j][c] = 0.f;

        #pragma unroll
        for (int kk = 0; kk < 4; kk++) {
            #pragma unroll
            for (int j2 = 0; j2 < 4; j2++) {
                const uint32_t off = swz_qk(j2*16 + brow_off, kk*32 + bkb_off);
                uint32_t bhh[4], bll[4];
                ldsm4(stb + off, bhh);
                ldsm4(stb + 8192 + off, bll);
                mma16816(S[2*j2],   qh[kk], bhh);
                mma16816(S[2*j2],   qh[kk], bll);
                mma16816(S[2*j2],   ql[kk], bhh);
                mma16816(S[2*j2+1], qh[kk], bhh + 2);
                mma16816(S[2*j2+1], qh[kk], bll + 2);
                mma16816(S[2*j2+1], ql[kk], bhh + 2);
            }
        }

        // ---- online softmax (base-2 domain) ----
        float mx0 = S[0][0], mx1 = S[0][2];
        #pragma unroll
        for (int j = 0; j < 8; j++) {
            mx0 = fmaxf(mx0, fmaxf(S[j][0], S[j][1]));
            mx1 = fmaxf(mx1, fmaxf(S[j][2], S[j][3]));
        }
        mx0 = fmaxf(mx0, __shfl_xor_sync(0xffffffffu, mx0, 1));
        mx0 = fmaxf(mx0, __shfl_xor_sync(0xffffffffu, mx0, 2));
        mx1 = fmaxf(mx1, __shfl_xor_sync(0xffffffffu, mx1, 1));
        mx1 = fmaxf(mx1, __shfl_xor_sync(0xffffffffu, mx1, 2));
        const float mn0 = fmaxf(m0, mx0);
        const float mn1 = fmaxf(m1, mx1);
        const float c0 = ex2(m0 - mn0);
        const float c1 = ex2(m1 - mn1);
        m0 = mn0; m1 = mn1;

        float sum0 = 0.f, sum1 = 0.f;
        #pragma unroll
        for (int j = 0; j < 8; j++) {
            S[j][0] = ex2(S[j][0] - mn0); sum0 += S[j][0];
            S[j][1] = ex2(S[j][1] - mn0); sum0 += S[j][1];
            S[j][2] = ex2(S[j][2] - mn1); sum1 += S[j][2];
            S[j][3] = ex2(S[j][3] - mn1); sum1 += S[j][3];
        }
        sum0 += __shfl_xor_sync(0xffffffffu, sum0, 1);
        sum0 += __shfl_xor_sync(0xffffffffu, sum0, 2);
        sum1 += __shfl_xor_sync(0xffffffffu, sum1, 1);
        sum1 += __shfl_xor_sync(0xffffffffu, sum1, 2);
        l0 = l0 * c0 + sum0;
        l1 = l1 * c1 + sum1;

        #pragma unroll
        for (int j = 0; j < 8; j++) {
            O[j][0] *= c0; O[j][1] *= c0;
            O[j][2] *= c1; O[j][3] *= c1;
        }

        // ---- O += P V (P from S fragments; Vt B-operand) ----
        #pragma unroll
        for (int kk = 0; kk < 4; kk++) {
            uint32_t phi[4], plo[4];
            split_pair(S[2*kk][0],   S[2*kk][1],   phi[0], plo[0]);
            split_pair(S[2*kk][2],   S[2*kk][3],   phi[1], plo[1]);
            split_pair(S[2*kk+1][0], S[2*kk+1][1], phi[2], plo[2]);
            split_pair(S[2*kk+1][2], S[2*kk+1][3], phi[3], plo[3]);
            #pragma unroll
            for (int jh = 0; jh < 4; jh++) {
                const uint32_t off = swz_qk(jh*16 + brow_off, kk*32 + bkb_off);
                uint32_t vh[4], vl[4];
                ldsm4(stb + 16384 + off, vh);
                ldsm4(stb + 24576 + off, vl);
                mma16816(O[2*jh],   phi, vh);
                mma16816(O[2*jh],   phi, vl);
                mma16816(O[2*jh],   plo, vh);
                mma16816(O[2*jh+1], phi, vh + 2);
                mma16816(O[2*jh+1], phi, vl + 2);
                mma16816(O[2*jh+1], plo, vh + 2);
            }
        }
        __syncthreads();
        if (kt + 2 < NN / 64) { load_stage(kt + 2, kt & 1); CP_COMMIT(); }
    }

    // ---- epilogue: normalize, write bf16 hi/lo to g_oh/g_ol [B,N,C] ----
    const float inv0 = 1.0f / l0;
    const float inv1 = 1.0f / l1;
    const int q0 = qt * 64 + wm + g;
    const size_t p0 = ((size_t)b * NN + q0) * CC + h * HD;
    const size_t p1 = ((size_t)b * NN + q0 + 8) * CC + h * HD;
    #pragma unroll
    for (int j = 0; j < 8; j++) {
        uint32_t hi, lo;
        split_pair(O[j][0] * inv0, O[j][1] * inv0, hi, lo);
        *(uint32_t*)(g_oh + p0 + 8*j + 2*t) = hi;
        *(uint32_t*)(g_ol + p0 + 8*j + 2*t) = lo;
        split_pair(O[j][2] * inv1, O[j][3] * inv1, hi, lo);
        *(uint32_t*)(g_oh + p1 + 8*j + 2*t) = hi;
        *(uint32_t*)(g_ol + p1 + 8*j + 2*t) = lo;
    }
}

// ---------------------------------------------------------------------------
extern "C" void kernel_launch(void* const* d_in, const int* in_sizes, int n_in,
                              void* d_out, int out_size)
{
    const float* x        = (const float*)d_in[0];
    const float* qkv_w    = (const float*)d_in[1];
    const float* qkv_b    = (const float*)d_in[2];
    const float* q_norm_w = (const float*)d_in[3];
    const float* k_norm_w = (const float*)d_in[4];
    const float* proj_w   = (const float*)d_in[5];
    const float* proj_b   = (const float*)d_in[6];
    float* out = (float*)d_out;

    __nv_bfloat16 *xh, *xl, *wth, *wtl, *pwth, *pwtl, *oh, *ol;
    cudaGetSymbolAddress((void**)&xh,   g_xh);
    cudaGetSymbolAddress((void**)&xl,   g_xl);
    cudaGetSymbolAddress((void**)&wth,  g_wth);
    cudaGetSymbolAddress((void**)&wtl,  g_wtl);
    cudaGetSymbolAddress((void**)&pwth, g_pwth);
    cudaGetSymbolAddress((void**)&pwtl, g_pwtl);
    cudaGetSymbolAddress((void**)&oh,   g_oh);
    cudaGetSymbolAddress((void**)&ol,   g_ol);

    cudaFuncSetAttribute(hmma_gemm_ca,
                         cudaFuncAttributeMaxDynamicSharedMemorySize, GEMM_SMEM);
    cudaFuncSetAttribute(attn_kernel,
                         cudaFuncAttributeMaxDynamicSharedMemorySize, ATTN_SMEM);

    // Operand conversion
    convert_x_kernel<<<MROWS * CC / 1024, 256>>>(x);
    {
        dim3 tb(32, 8);
        transpose_convert_kernel<<<dim3(QKVN/32, CC/32), tb>>>(qkv_w, wth, wtl, CC, QKVN);
        transpose_convert_kernel<<<dim3(CC/32, CC/32), tb>>>(proj_w, pwth, pwtl, CC, CC);
    }
    // QKV GEMM + bias + fused rmsnorm -> bf16 hi/lo q/k/v
    {
        dim3 grid(QKVN / 128, MROWS / 128);   // 24 x 32
        hmma_gemm_ca<<<grid, 256, GEMM_SMEM>>>(xh, xl, wth, wtl, qkv_b, nullptr,
                                               q_norm_w, k_norm_w, 0);
    }
    // v transpose (bf16 -> [B,H,hd,N])
    {
        dim3 tb(32, 8);
        transpose_v_kernel<<<dim3(NN/32, HD/32, BB*HH), tb>>>();
    }
    // Flash attention (all-bf16, cp.async double buffered)
    {
        dim3 grid(NN / 64, BB * HH);          // 32 x 32
        attn_kernel<<<grid, 128, ATTN_SMEM>>>();
    }
    // Output projection
    {
        dim3 grid(CC / 128, MROWS / 128);     // 8 x 32
        hmma_gemm_ca<<<grid, 256, GEMM_SMEM>>>(oh, ol, pwth, pwtl, proj_b, out,
                                               nullptr, nullptr, 1);
    }
}